// round 12
// baseline (speedup 1.0000x reference)
#include <cuda_runtime.h>
#include <cstdint>

// Problem constants
#define BB   4
#define C3   256
#define H3   48
#define L3   (H3*H3)          // 2304
#define C2   128
#define H2   96
#define L2n  (H2*H2)          // 9216
#define C1   64
#define H1   192
#define L1n  (H1*H1)          // 36864
#define EPSN 1e-12f

#define BK2 32
#define GEMM_SMEM (2 * BK2 * 128 * 2 * 4)      // 65536 bytes

#define CHQ 8
#define MAXARG_SMEM (10 * L3 * 4)              // 92160 bytes dynamic

// side_kernel block counts
#define NSQB 72                                 // 9 tiles x 2 tensors x 4 batches
#define NT3  2304
#define NT2  4608
#define NT1  9216
#define NSIDE (NSQB + NT3 + NT2 + NT1)          // 16200

// ---------------- scratch (static device globals; no allocation) -------------
__device__ __align__(16) float g_P[(size_t)BB * L3 * L3];   // [b][lq][lk]  ~85MB
__device__ __align__(16) float g_G[(size_t)BB * L3 * L3];   // x-pass of shifted sum
__device__ __align__(16) float g_cl3T[(size_t)BB * L3 * C3];  // [b][pix][c]
__device__ __align__(16) float g_cl2T[(size_t)BB * L2n * C2];
__device__ __align__(16) float g_cl1T[(size_t)BB * L1n * C1];
__device__ __align__(16) float g_nrm[2][BB * L3];     // 0: nq(img) norm, 1: 1/nk(ref)
__device__ int   g_idx[BB * L3];                      // argmax index per query

// ---------------- helpers -----------------------------------------------------
__device__ __forceinline__ void cp_async16(uint32_t smem, const void* gmem) {
    asm volatile("cp.async.cg.shared.global [%0], [%1], 16;\n" :: "r"(smem), "l"(gmem));
}
__device__ __forceinline__ void cp_commit() {
    asm volatile("cp.async.commit_group;\n" ::: "memory");
}
__device__ __forceinline__ void cp_wait0() {
    asm volatile("cp.async.wait_group 0;\n" ::: "memory");
}
// packed fp32x2 FMA: d = a*b + d  (componentwise, exact fp32 semantics)
__device__ __forceinline__ void fma2(unsigned long long& d, unsigned long long a,
                                     unsigned long long b) {
    asm("fma.rn.f32x2 %0, %1, %2, %0;" : "+l"(d) : "l"(a), "l"(b));
}
__device__ __forceinline__ unsigned long long bcast2(float x) {
    unsigned long long r;
    asm("mov.b64 %0, {%1, %1};" : "=l"(r) : "f"(x));
    return r;
}

// ---------------- side kernel: 3 transposes + fused sqsum/boxnorm ------------
__global__ void __launch_bounds__(256) side_kernel(const float* __restrict__ img,
                                                   const float* __restrict__ ref,
                                                   const float* __restrict__ cl1,
                                                   const float* __restrict__ cl2,
                                                   const float* __restrict__ cl3) {
    __shared__ float sbuf[1056];                 // transpose 32x33; sqsumbox uses 324
    int j = blockIdx.x;
    int tid = threadIdx.x;

    if (j < NSQB) {
        // ---- fused per-pixel sqnorm + 3x3 box-sum -> patch norm ----
        int tile = j % 9, which = (j / 9) & 1, b = j / 18;
        const float* src = ((which == 0) ? img : ref) + (size_t)b * C3 * L3;
        int ty0 = (tile / 3) * 16, tx0 = (tile % 3) * 16;
        for (int p = tid; p < 324; p += 256) {
            int py = ty0 + p / 18 - 1, px = tx0 + p % 18 - 1;
            float s = 0.f;
            if ((unsigned)py < H3 && (unsigned)px < H3) {
                const float* sp = src + py * H3 + px;
                #pragma unroll 4
                for (int c = 0; c < C3; c++) {
                    float v = sp[(size_t)c * L3];
                    s += v * v;
                }
            }
            sbuf[p] = s;
        }
        __syncthreads();
        {
            int py = tid / 16, px = tid % 16;       // all 256 threads
            float acc = 0.f;
            #pragma unroll
            for (int dy = 0; dy < 3; dy++)
                #pragma unroll
                for (int dx = 0; dx < 3; dx++)
                    acc += sbuf[(py + dy) * 18 + px + dx];
            float n = fmaxf(sqrtf(acc), EPSN);
            g_nrm[which][b * L3 + (ty0 + py) * H3 + tx0 + px] = which ? (1.0f / n) : n;
        }
        return;
    }

    // ---- transpose cl -> channel-last ----
    int q = j - NSQB;
    const float* src; float* dst; int C, L;
    if (q < NT3)            { src = cl3; dst = g_cl3T; C = C3; L = L3; }
    else if (q < NT3 + NT2) { q -= NT3;  src = cl2; dst = g_cl2T; C = C2; L = L2n; }
    else                    { q -= NT3 + NT2; src = cl1; dst = g_cl1T; C = C1; L = L1n; }
    int nl = L / 32, nc = C / 32;
    int l0 = (q % nl) * 32, c0 = ((q / nl) % nc) * 32, b = q / (nl * nc);
    const float* s = src + (size_t)b * C * L;
    float* d = dst + (size_t)b * L * C;
    int txx = tid % 32, tyy = tid / 32;
    #pragma unroll
    for (int i = tyy; i < 32; i += 8)
        sbuf[i * 33 + txx] = s[(size_t)(c0 + i) * L + l0 + txx];
    __syncthreads();
    #pragma unroll
    for (int i = tyy; i < 32; i += 8)
        d[(size_t)(l0 + i) * C + c0 + txx] = sbuf[txx * 33 + i];
}

// ---------------- 4) SGEMM via packed FFMA2, BK=32, dynamic smem -------------
__global__ void __launch_bounds__(256, 2) gemm_kernel(const float* __restrict__ img,
                                                      const float* __restrict__ ref) {
    // release PDL dependents immediately: side_kernel may co-schedule
    asm volatile("griddepcontrol.launch_dependents;" ::: "memory");

    extern __shared__ __align__(16) float sm[];
    const int b  = blockIdx.z;
    const int m0 = blockIdx.y * 128;
    const int n0 = blockIdx.x * 128;
    const float* A  = img + (size_t)b * C3 * L3;   // [k][m]
    const float* Bm = ref + (size_t)b * C3 * L3;   // [k][n]
    float* Cc = g_P + (size_t)b * L3 * L3;

    const int tid = threadIdx.x;
    const int lr  = tid >> 5;            // 0..7
    const int lc  = (tid & 31) * 4;
    const int tx  = tid & 15;
    const int ty  = tid >> 4;

    const float* gA[4]; const float* gB[4];
    uint32_t sA[2][4], sB[2][4];
    #pragma unroll
    for (int i = 0; i < 4; i++) {
        gA[i] = &A [(size_t)(lr + 8 * i) * L3 + m0 + lc];
        gB[i] = &Bm[(size_t)(lr + 8 * i) * L3 + n0 + lc];
        #pragma unroll
        for (int u = 0; u < 2; u++) {
            sA[u][i] = (uint32_t)__cvta_generic_to_shared(
                &sm[u * 4096 + (lr + 8 * i) * 128 + lc]);
            sB[u][i] = (uint32_t)__cvta_generic_to_shared(
                &sm[8192 + u * 4096 + (lr + 8 * i) * 128 + lc]);
        }
    }
    const size_t kstep = (size_t)BK2 * L3;

    unsigned long long acc2[8][4];
    #pragma unroll
    for (int i = 0; i < 8; i++)
        #pragma unroll
        for (int j = 0; j < 4; j++) acc2[i][j] = 0ULL;

    #pragma unroll
    for (int i = 0; i < 4; i++) { cp_async16(sA[0][i], gA[i]); cp_async16(sB[0][i], gB[i]); }
    cp_commit();

    int buf = 0;
    for (int ks = 0; ks < C3 / BK2; ks++) {
        cp_wait0();
        __syncthreads();

        if (ks + 1 < C3 / BK2) {
            size_t off = (size_t)(ks + 1) * kstep;
            int nb = buf ^ 1;
            #pragma unroll
            for (int i = 0; i < 4; i++) {
                cp_async16(sA[nb][i], gA[i] + off);
                cp_async16(sB[nb][i], gB[i] + off);
            }
            cp_commit();
        }

        const float* Ab = &sm[buf * 4096];
        const float* Bb = &sm[8192 + buf * 4096];
        #pragma unroll 8
        for (int kk = 0; kk < BK2; kk++) {
            float a[8];
            *(float4*)&a[0] = *(const float4*)&Ab[kk * 128 + ty * 4];
            *(float4*)&a[4] = *(const float4*)&Ab[kk * 128 + 64 + ty * 4];
            float4 bv0 = *(const float4*)&Bb[kk * 128 + tx * 4];
            float4 bv1 = *(const float4*)&Bb[kk * 128 + 64 + tx * 4];
            unsigned long long b2[4];
            b2[0] = ((unsigned long long*)&bv0)[0];
            b2[1] = ((unsigned long long*)&bv0)[1];
            b2[2] = ((unsigned long long*)&bv1)[0];
            b2[3] = ((unsigned long long*)&bv1)[1];
            #pragma unroll
            for (int i = 0; i < 8; i++) {
                unsigned long long a2 = bcast2(a[i]);
                fma2(acc2[i][0], a2, b2[0]);
                fma2(acc2[i][1], a2, b2[1]);
                fma2(acc2[i][2], a2, b2[2]);
                fma2(acc2[i][3], a2, b2[3]);
            }
        }
        buf ^= 1;
    }

    #pragma unroll
    for (int i = 0; i < 8; i++) {
        int m = m0 + ((i < 4) ? (ty * 4 + i) : (64 + ty * 4 + i - 4));
        float* row = Cc + (size_t)m * L3;
        *(unsigned long long*)&row[n0 + tx * 4]          = acc2[i][0];
        *(unsigned long long*)&row[n0 + tx * 4 + 2]      = acc2[i][1];
        *(unsigned long long*)&row[n0 + 64 + tx * 4]     = acc2[i][2];
        *(unsigned long long*)&row[n0 + 64 + tx * 4 + 2] = acc2[i][3];
    }
}

// ---------------- 5a) x-pass: G[r][c] = A[c-1] + B[c] + C[c+1], 4 rows/block -
#define SRS 2312
__global__ void gpass1_kernel() {
    __shared__ __align__(16) float sR[6 * SRS];
    int r0 = blockIdx.x * 4, b = blockIdx.y;
    const float* Pb = g_P + (size_t)b * L3 * L3;
    float* Gb = g_G + (size_t)b * L3 * L3;
    int tid = threadIdx.x;

    #pragma unroll
    for (int i = 0; i < 6; i++) {
        int rr = min(max(r0 - 1 + i, 0), L3 - 1);   // clamped rows never used
        const float4* src = (const float4*)(Pb + (size_t)rr * L3);
        float4* dst = (float4*)&sR[i * SRS + 4];
        for (int g = tid; g < 576; g += 256) dst[g] = src[g];
    }
    __syncthreads();

    #pragma unroll
    for (int j = 0; j < 4; j++) {
        int r = r0 + j;
        int xq = r % H3;
        const float* Aj = &sR[j * SRS + 4];
        const float* Bj = &sR[(j + 1) * SRS + 4];
        const float* Cj = &sR[(j + 2) * SRS + 4];
        float* gr = Gb + (size_t)r * L3;
        bool hasA = (xq != 0), hasC = (xq != H3 - 1);

        if (hasA && hasC) {
            for (int g = tid; g < 576; g += 256) {
                int c = g * 4;
                int m = (g % 12) * 4;
                float4 bv = *(const float4*)&Bj[c];
                float a0 = (m != 0) ? Aj[c - 1] : 0.f;
                float c3 = (m != 44) ? Cj[c + 4] : 0.f;
                float4 o;
                o.x = a0        + bv.x + Cj[c + 1];
                o.y = Aj[c]     + bv.y + Cj[c + 2];
                o.z = Aj[c + 1] + bv.z + Cj[c + 3];
                o.w = Aj[c + 2] + bv.w + c3;
                *(float4*)&gr[c] = o;
            }
        } else if (!hasA) {
            for (int g = tid; g < 576; g += 256) {
                int c = g * 4;
                int m = (g % 12) * 4;
                float4 bv = *(const float4*)&Bj[c];
                float c3 = (m != 44) ? Cj[c + 4] : 0.f;
                float4 o;
                o.x = bv.x + Cj[c + 1];
                o.y = bv.y + Cj[c + 2];
                o.z = bv.z + Cj[c + 3];
                o.w = bv.w + c3;
                *(float4*)&gr[c] = o;
            }
        } else {
            for (int g = tid; g < 576; g += 256) {
                int c = g * 4;
                int m = (g % 12) * 4;
                float4 bv = *(const float4*)&Bj[c];
                float a0 = (m != 0) ? Aj[c - 1] : 0.f;
                float4 o;
                o.x = a0        + bv.x;
                o.y = Aj[c]     + bv.y;
                o.z = Aj[c + 1] + bv.z;
                o.w = Aj[c + 2] + bv.w;
                *(float4*)&gr[c] = o;
            }
        }
    }
}

// ---------------- 5b) chain-of-8 y-pass + max/argmax -------------------------
// Block = one vertical chain (fixed xq, yq0..yq0+7). Stages 10 G rows in smem;
// queries share rows. Column shifts +-48 are float4-aligned (+-12 groups).
__global__ void __launch_bounds__(256) maxarg_kernel(float* __restrict__ outS) {
    extern __shared__ __align__(16) float sG[];   // 10 rows x 2304 floats
    __shared__ float sv[CHQ][256];
    __shared__ int   si[CHQ][256];
    int b = blockIdx.y;
    int xq  = blockIdx.x % H3;
    int yq0 = (blockIdx.x / H3) * CHQ;
    int tid = threadIdx.x;
    const float* Gb = g_G + (size_t)b * L3 * L3;

    // stage 10 G rows: yr = yq0-1+j (zeros when out of range)
    #pragma unroll
    for (int j = 0; j < 10; j++) {
        int yr = yq0 - 1 + j;
        float4* dst = (float4*)&sG[j * L3];
        if ((unsigned)yr < H3) {
            const float4* src = (const float4*)(Gb + ((size_t)yr * H3 + xq) * L3);
            for (int g = tid; g < 576; g += 256) dst[g] = src[g];
        } else {
            float4 z = make_float4(0.f, 0.f, 0.f, 0.f);
            for (int g = tid; g < 576; g += 256) dst[g] = z;
        }
    }
    __syncthreads();

    const float4* rnk4 = (const float4*)&g_nrm[1][b * L3];
    float best[CHQ]; int bi[CHQ];
    #pragma unroll
    for (int q = 0; q < CHQ; q++) { best[q] = -1e30f; bi[q] = 0; }

    float4 z4 = make_float4(0.f, 0.f, 0.f, 0.f);
    for (int gi = tid; gi < 576; gi += 256) {
        bool m0 = (gi >= 12), m2 = (gi < 564);
        float4 rk = rnk4[gi];
        int c = gi * 4;
        #pragma unroll
        for (int q = 0; q < CHQ; q++) {
            float4 v0 = m0 ? *(const float4*)&sG[q * L3 + c - 48] : z4;
            float4 v1 =      *(const float4*)&sG[(q + 1) * L3 + c];
            float4 v2 = m2 ? *(const float4*)&sG[(q + 2) * L3 + c + 48] : z4;
            float s0 = (v0.x + v1.x + v2.x) * rk.x;
            float s1 = (v0.y + v1.y + v2.y) * rk.y;
            float s2 = (v0.z + v1.z + v2.z) * rk.z;
            float s3 = (v0.w + v1.w + v2.w) * rk.w;
            if (s0 > best[q]) { best[q] = s0; bi[q] = c; }
            if (s1 > best[q]) { best[q] = s1; bi[q] = c + 1; }
            if (s2 > best[q]) { best[q] = s2; bi[q] = c + 2; }
            if (s3 > best[q]) { best[q] = s3; bi[q] = c + 3; }
        }
    }

    #pragma unroll
    for (int q = 0; q < CHQ; q++) { sv[q][tid] = best[q]; si[q][tid] = bi[q]; }
    __syncthreads();

    int w = tid >> 5, lane = tid & 31;
    if (w < CHQ) {
        float bb = sv[w][lane]; int ii = si[w][lane];
        #pragma unroll
        for (int k = 1; k < 8; k++) {
            float o = sv[w][lane + k * 32]; int oi = si[w][lane + k * 32];
            if (o > bb || (o == bb && oi < ii)) { bb = o; ii = oi; }
        }
        #pragma unroll
        for (int s = 16; s > 0; s >>= 1) {
            float o = __shfl_down_sync(0xffffffffu, bb, s);
            int  oi = __shfl_down_sync(0xffffffffu, ii, s);
            if (o > bb || (o == bb && oi < ii)) { bb = o; ii = oi; }
        }
        if (lane == 0) {
            int lq = (yq0 + w) * H3 + xq;
            g_idx[b * L3 + lq] = ii;
            outS[b * L3 + lq]  = bb / g_nrm[0][b * L3 + lq];
        }
    }
}

// ---------------- 6) fused gather + fold-normalize (precomputed cell table) --
__global__ void transfer_kernel(float* __restrict__ out, int C, int W, int ls, int sel,
                                int xpc) {
    const float* clT = (sel == 0) ? g_cl3T : (sel == 1) ? g_cl2T : g_cl1T;
    __shared__ __align__(16) float acc[3456];    // xpc*(C+8) <= 3456 floats
    __shared__ __align__(16) int4 ent[3][14];    // {dxs, base4, ok, pad}
    __shared__ float sinv[12];
    int b = blockIdx.y, y = blockIdx.x;
    int xlo = blockIdx.z * xpc;
    int tid = threadIdx.x;
    int cpg  = C >> 2;
    int cg   = tid & (cpg - 1);
    int xsub = tid / cpg;
    int ppp  = 256 / cpg;
    int astr = C + 8;

    int tyq  = y >> ls;
    int txq0 = xlo >> ls;
    const int* idxb = g_idx + b * L3;

    if (tid < 42) {
        int a = tid / 14, xi = tid % 14;
        int xq = txq0 - 1 + xi;
        int yq = tyq - 1 + a;
        int dxs = 0, base4 = 0, ok = 0;
        if ((unsigned)xq < H3 && (unsigned)yq < H3) {
            int idx = idxb[yq * H3 + xq];
            int yk = idx / H3, xk = idx % H3;
            int ys = y + ((yk - yq) << ls);
            if ((unsigned)ys < (unsigned)W) {
                ok = 1;
                base4 = ys * W * (C >> 2);
            }
            dxs = (xk - xq) << ls;
        }
        ent[a][xi] = make_int4(dxs, base4, ok, 0);
    }
    if (tid < 12) {
        int txq = txq0 + tid;
        int nvx = 1 + (txq > 0) + (txq < H3 - 1);
        int nvy = 1 + (tyq > 0) + (tyq < H3 - 1);
        sinv[tid] = 1.0f / (float)(nvx * nvy);
    }
    __syncthreads();

    const float4* f4b = (const float4*)(clT + (size_t)b * W * W * C);

    for (int xo = 0; xo < xpc; xo += ppp) {
        int x = xlo + xo + xsub;
        int xib = (x >> ls) - txq0;
        float4 sum = make_float4(0.f, 0.f, 0.f, 0.f);
        #pragma unroll
        for (int a = 0; a < 3; a++) {
            #pragma unroll
            for (int dx = 0; dx < 3; dx++) {
                int4 e = ent[a][xib + dx];
                int xs = x + e.x;
                if (e.z && (unsigned)xs < (unsigned)W) {
                    float4 v = f4b[e.y + xs * cpg + cg];
                    sum.x += v.x; sum.y += v.y; sum.z += v.z; sum.w += v.w;
                }
            }
        }
        float ic = sinv[xib];
        *(float4*)&acc[(xo + xsub) * astr + cg * 4] =
            make_float4(sum.x * ic, sum.y * ic, sum.z * ic, sum.w * ic);
    }
    __syncthreads();

    size_t ob = (size_t)b * C * W * W + (size_t)y * W + xlo;
    int tot = C * xpc;
    for (int i = tid; i < tot; i += 256) {
        int c = i / xpc, x = i % xpc;
        out[ob + (size_t)c * W * W + x] = acc[x * astr + c];
    }
}

// ---------------- launch ------------------------------------------------------
extern "C" void kernel_launch(void* const* d_in, const int* in_sizes, int n_in,
                              void* d_out, int out_size) {
    const float* img = (const float*)d_in[0];   // dh_img_lv3 [4,256,48,48]
    const float* ref = (const float*)d_in[1];   // dh_ref_lv3 [4,256,48,48]
    const float* cl1 = (const float*)d_in[2];   // cl_ref_lv1 [4,64,192,192]
    const float* cl2 = (const float*)d_in[3];   // cl_ref_lv2 [4,128,96,96]
    const float* cl3 = (const float*)d_in[4];   // cl_ref_lv3 [4,256,48,48]

    float* outS  = (float*)d_out;               // [4,1,48,48]
    float* outT3 = outS  + BB * L3;             // [4,256,48,48]
    float* outT2 = outT3 + (size_t)BB * C3 * L3;    // [4,128,96,96]
    float* outT1 = outT2 + (size_t)BB * C2 * L2n;   // [4,64,192,192]

    cudaFuncSetAttribute(gemm_kernel,
                         cudaFuncAttributeMaxDynamicSharedMemorySize, GEMM_SMEM);
    cudaFuncSetAttribute(maxarg_kernel,
                         cudaFuncAttributeMaxDynamicSharedMemorySize, MAXARG_SMEM);

    // 0: GEMM (triggers PDL dependents at start)
    gemm_kernel<<<dim3(L3 / 128, L3 / 128, BB), 256, GEMM_SMEM>>>(img, ref);

    // 1: side work (transposes + norms), PDL so it fills gemm's gaps/tail
    {
        cudaLaunchConfig_t cfg = {};
        cfg.gridDim = dim3(NSIDE);
        cfg.blockDim = dim3(256);
        cfg.dynamicSmemBytes = 0;
        cfg.stream = 0;
        cudaLaunchAttribute at;
        at.id = cudaLaunchAttributeProgrammaticStreamSerialization;
        at.val.programmaticStreamSerializationAllowed = 1;
        cfg.attrs = &at;
        cfg.numAttrs = 1;
        cudaError_t e = cudaLaunchKernelEx(&cfg, side_kernel, img, ref, cl1, cl2, cl3);
        if (e != cudaSuccess) {
            side_kernel<<<NSIDE, 256>>>(img, ref, cl1, cl2, cl3);
        }
    }

    // 2: x-pass (normal launch: full barrier on gemm + side)
    gpass1_kernel<<<dim3(L3 / 4, BB), 256>>>();

    // 3: chain y-pass + argmax (profiled slot)
    maxarg_kernel<<<dim3(H3 * (H3 / CHQ), BB), 256, MAXARG_SMEM>>>(outS);

    // 4-6: transfers
    transfer_kernel<<<dim3(H3, BB, 4), 256>>>(outT3, C3, H3, 0, 0, H3 / 4);
    transfer_kernel<<<dim3(H2, BB, 4), 256>>>(outT2, C2, H2, 1, 1, H2 / 4);
    transfer_kernel<<<dim3(H1, BB, 4), 256>>>(outT1, C1, H1, 2, 2, H1 / 4);
}

// round 13
// speedup vs baseline: 1.1034x; 1.1034x over previous
#include <cuda_runtime.h>
#include <cstdint>

// Problem constants
#define BB   4
#define C3   256
#define H3   48
#define L3   (H3*H3)          // 2304
#define C2   128
#define H2   96
#define L2n  (H2*H2)          // 9216
#define C1   64
#define H1   192
#define L1n  (H1*H1)          // 36864
#define EPSN 1e-12f

#define BK2 32
#define GEMM_SMEM (2 * BK2 * 128 * 2 * 4)      // 65536 bytes

// side_kernel block counts
#define NSQB 72                                 // 9 tiles x 2 tensors x 4 batches
#define NT3  2304
#define NT2  4608
#define NT1  9216
#define NSIDE (NSQB + NT3 + NT2 + NT1)          // 16200

// merged transfer block counts
#define XB3 768                                 // 48*4*4
#define XB2 1536                                // 96*4*4
#define XB1 3072                                // 192*4*4
#define NXFER (XB3 + XB2 + XB1)                 // 5376

// ---------------- scratch (static device globals; no allocation) -------------
__device__ __align__(16) float g_P[(size_t)BB * L3 * L3];   // [b][lq][lk]  ~85MB
__device__ __align__(16) float g_G[(size_t)BB * L3 * L3];   // x-pass of shifted sum
__device__ __align__(16) float g_cl3T[(size_t)BB * L3 * C3];  // [b][pix][c]
__device__ __align__(16) float g_cl2T[(size_t)BB * L2n * C2];
__device__ __align__(16) float g_cl1T[(size_t)BB * L1n * C1];
__device__ __align__(16) float g_nrm[2][BB * L3];     // 0: nq(img) norm, 1: 1/nk(ref)
__device__ int   g_idx[BB * L3];                      // argmax index per query
__device__ __align__(16) float g_zero[16];            // stays zero (never written)

// ---------------- helpers -----------------------------------------------------
__device__ __forceinline__ void cp_async16(uint32_t smem, const void* gmem) {
    asm volatile("cp.async.cg.shared.global [%0], [%1], 16;\n" :: "r"(smem), "l"(gmem));
}
__device__ __forceinline__ void cp_commit() {
    asm volatile("cp.async.commit_group;\n" ::: "memory");
}
__device__ __forceinline__ void cp_wait0() {
    asm volatile("cp.async.wait_group 0;\n" ::: "memory");
}
// packed fp32x2 FMA: d = a*b + d  (componentwise, exact fp32 semantics)
__device__ __forceinline__ void fma2(unsigned long long& d, unsigned long long a,
                                     unsigned long long b) {
    asm("fma.rn.f32x2 %0, %1, %2, %0;" : "+l"(d) : "l"(a), "l"(b));
}
__device__ __forceinline__ unsigned long long bcast2(float x) {
    unsigned long long r;
    asm("mov.b64 %0, {%1, %1};" : "=l"(r) : "f"(x));
    return r;
}

// ---------------- side kernel: 3 transposes + fused sqsum/boxnorm ------------
__global__ void __launch_bounds__(256) side_kernel(const float* __restrict__ img,
                                                   const float* __restrict__ ref,
                                                   const float* __restrict__ cl1,
                                                   const float* __restrict__ cl2,
                                                   const float* __restrict__ cl3) {
    __shared__ float sbuf[1056];                 // transpose 32x33; sqsumbox uses 324
    int j = blockIdx.x;
    int tid = threadIdx.x;

    if (j < NSQB) {
        // ---- fused per-pixel sqnorm + 3x3 box-sum -> patch norm ----
        int tile = j % 9, which = (j / 9) & 1, b = j / 18;
        const float* src = ((which == 0) ? img : ref) + (size_t)b * C3 * L3;
        int ty0 = (tile / 3) * 16, tx0 = (tile % 3) * 16;
        for (int p = tid; p < 324; p += 256) {
            int py = ty0 + p / 18 - 1, px = tx0 + p % 18 - 1;
            float s = 0.f;
            if ((unsigned)py < H3 && (unsigned)px < H3) {
                const float* sp = src + py * H3 + px;
                #pragma unroll 4
                for (int c = 0; c < C3; c++) {
                    float v = sp[(size_t)c * L3];
                    s += v * v;
                }
            }
            sbuf[p] = s;
        }
        __syncthreads();
        {
            int py = tid / 16, px = tid % 16;       // all 256 threads
            float acc = 0.f;
            #pragma unroll
            for (int dy = 0; dy < 3; dy++)
                #pragma unroll
                for (int dx = 0; dx < 3; dx++)
                    acc += sbuf[(py + dy) * 18 + px + dx];
            float n = fmaxf(sqrtf(acc), EPSN);
            g_nrm[which][b * L3 + (ty0 + py) * H3 + tx0 + px] = which ? (1.0f / n) : n;
        }
        return;
    }

    // ---- transpose cl -> channel-last ----
    int q = j - NSQB;
    const float* src; float* dst; int C, L;
    if (q < NT3)            { src = cl3; dst = g_cl3T; C = C3; L = L3; }
    else if (q < NT3 + NT2) { q -= NT3;  src = cl2; dst = g_cl2T; C = C2; L = L2n; }
    else                    { q -= NT3 + NT2; src = cl1; dst = g_cl1T; C = C1; L = L1n; }
    int nl = L / 32, nc = C / 32;
    int l0 = (q % nl) * 32, c0 = ((q / nl) % nc) * 32, b = q / (nl * nc);
    const float* s = src + (size_t)b * C * L;
    float* d = dst + (size_t)b * L * C;
    int txx = tid % 32, tyy = tid / 32;
    #pragma unroll
    for (int i = tyy; i < 32; i += 8)
        sbuf[i * 33 + txx] = s[(size_t)(c0 + i) * L + l0 + txx];
    __syncthreads();
    #pragma unroll
    for (int i = tyy; i < 32; i += 8)
        d[(size_t)(l0 + i) * C + c0 + txx] = sbuf[txx * 33 + i];
}

// ---------------- 4) SGEMM via packed FFMA2, BK=32, dynamic smem -------------
__global__ void __launch_bounds__(256, 2) gemm_kernel(const float* __restrict__ img,
                                                      const float* __restrict__ ref) {
    // release PDL dependents immediately: side_kernel may co-schedule
    asm volatile("griddepcontrol.launch_dependents;" ::: "memory");

    extern __shared__ __align__(16) float sm[];
    const int b  = blockIdx.z;
    const int m0 = blockIdx.y * 128;
    const int n0 = blockIdx.x * 128;
    const float* A  = img + (size_t)b * C3 * L3;   // [k][m]
    const float* Bm = ref + (size_t)b * C3 * L3;   // [k][n]
    float* Cc = g_P + (size_t)b * L3 * L3;

    const int tid = threadIdx.x;
    const int lr  = tid >> 5;            // 0..7
    const int lc  = (tid & 31) * 4;
    const int tx  = tid & 15;
    const int ty  = tid >> 4;

    const float* gA[4]; const float* gB[4];
    uint32_t sA[2][4], sB[2][4];
    #pragma unroll
    for (int i = 0; i < 4; i++) {
        gA[i] = &A [(size_t)(lr + 8 * i) * L3 + m0 + lc];
        gB[i] = &Bm[(size_t)(lr + 8 * i) * L3 + n0 + lc];
        #pragma unroll
        for (int u = 0; u < 2; u++) {
            sA[u][i] = (uint32_t)__cvta_generic_to_shared(
                &sm[u * 4096 + (lr + 8 * i) * 128 + lc]);
            sB[u][i] = (uint32_t)__cvta_generic_to_shared(
                &sm[8192 + u * 4096 + (lr + 8 * i) * 128 + lc]);
        }
    }
    const size_t kstep = (size_t)BK2 * L3;

    unsigned long long acc2[8][4];
    #pragma unroll
    for (int i = 0; i < 8; i++)
        #pragma unroll
        for (int j = 0; j < 4; j++) acc2[i][j] = 0ULL;

    #pragma unroll
    for (int i = 0; i < 4; i++) { cp_async16(sA[0][i], gA[i]); cp_async16(sB[0][i], gB[i]); }
    cp_commit();

    int buf = 0;
    for (int ks = 0; ks < C3 / BK2; ks++) {
        cp_wait0();
        __syncthreads();

        if (ks + 1 < C3 / BK2) {
            size_t off = (size_t)(ks + 1) * kstep;
            int nb = buf ^ 1;
            #pragma unroll
            for (int i = 0; i < 4; i++) {
                cp_async16(sA[nb][i], gA[i] + off);
                cp_async16(sB[nb][i], gB[i] + off);
            }
            cp_commit();
        }

        const float* Ab = &sm[buf * 4096];
        const float* Bb = &sm[8192 + buf * 4096];
        #pragma unroll 8
        for (int kk = 0; kk < BK2; kk++) {
            float a[8];
            *(float4*)&a[0] = *(const float4*)&Ab[kk * 128 + ty * 4];
            *(float4*)&a[4] = *(const float4*)&Ab[kk * 128 + 64 + ty * 4];
            float4 bv0 = *(const float4*)&Bb[kk * 128 + tx * 4];
            float4 bv1 = *(const float4*)&Bb[kk * 128 + 64 + tx * 4];
            unsigned long long b2[4];
            b2[0] = ((unsigned long long*)&bv0)[0];
            b2[1] = ((unsigned long long*)&bv0)[1];
            b2[2] = ((unsigned long long*)&bv1)[0];
            b2[3] = ((unsigned long long*)&bv1)[1];
            #pragma unroll
            for (int i = 0; i < 8; i++) {
                unsigned long long a2 = bcast2(a[i]);
                fma2(acc2[i][0], a2, b2[0]);
                fma2(acc2[i][1], a2, b2[1]);
                fma2(acc2[i][2], a2, b2[2]);
                fma2(acc2[i][3], a2, b2[3]);
            }
        }
        buf ^= 1;
    }

    #pragma unroll
    for (int i = 0; i < 8; i++) {
        int m = m0 + ((i < 4) ? (ty * 4 + i) : (64 + ty * 4 + i - 4));
        float* row = Cc + (size_t)m * L3;
        *(unsigned long long*)&row[n0 + tx * 4]          = acc2[i][0];
        *(unsigned long long*)&row[n0 + tx * 4 + 2]      = acc2[i][1];
        *(unsigned long long*)&row[n0 + 64 + tx * 4]     = acc2[i][2];
        *(unsigned long long*)&row[n0 + 64 + tx * 4 + 2] = acc2[i][3];
    }
}

// ---------------- 5a) x-pass: G[r][c] = A[c-1] + B[c] + C[c+1], 4 rows/block -
#define SRS 2312
__global__ void gpass1_kernel() {
    __shared__ __align__(16) float sR[6 * SRS];
    int r0 = blockIdx.x * 4, b = blockIdx.y;
    const float* Pb = g_P + (size_t)b * L3 * L3;
    float* Gb = g_G + (size_t)b * L3 * L3;
    int tid = threadIdx.x;

    #pragma unroll
    for (int i = 0; i < 6; i++) {
        int rr = min(max(r0 - 1 + i, 0), L3 - 1);   // clamped rows never used
        const float4* src = (const float4*)(Pb + (size_t)rr * L3);
        float4* dst = (float4*)&sR[i * SRS + 4];
        for (int g = tid; g < 576; g += 256) dst[g] = src[g];
    }
    __syncthreads();

    #pragma unroll
    for (int j = 0; j < 4; j++) {
        int r = r0 + j;
        int xq = r % H3;
        const float* Aj = &sR[j * SRS + 4];
        const float* Bj = &sR[(j + 1) * SRS + 4];
        const float* Cj = &sR[(j + 2) * SRS + 4];
        float* gr = Gb + (size_t)r * L3;
        bool hasA = (xq != 0), hasC = (xq != H3 - 1);

        if (hasA && hasC) {
            for (int g = tid; g < 576; g += 256) {
                int c = g * 4;
                int m = (g % 12) * 4;
                float4 bv = *(const float4*)&Bj[c];
                float a0 = (m != 0) ? Aj[c - 1] : 0.f;
                float c3 = (m != 44) ? Cj[c + 4] : 0.f;
                float4 o;
                o.x = a0        + bv.x + Cj[c + 1];
                o.y = Aj[c]     + bv.y + Cj[c + 2];
                o.z = Aj[c + 1] + bv.z + Cj[c + 3];
                o.w = Aj[c + 2] + bv.w + c3;
                *(float4*)&gr[c] = o;
            }
        } else if (!hasA) {
            for (int g = tid; g < 576; g += 256) {
                int c = g * 4;
                int m = (g % 12) * 4;
                float4 bv = *(const float4*)&Bj[c];
                float c3 = (m != 44) ? Cj[c + 4] : 0.f;
                float4 o;
                o.x = bv.x + Cj[c + 1];
                o.y = bv.y + Cj[c + 2];
                o.z = bv.z + Cj[c + 3];
                o.w = bv.w + c3;
                *(float4*)&gr[c] = o;
            }
        } else {
            for (int g = tid; g < 576; g += 256) {
                int c = g * 4;
                int m = (g % 12) * 4;
                float4 bv = *(const float4*)&Bj[c];
                float a0 = (m != 0) ? Aj[c - 1] : 0.f;
                float4 o;
                o.x = a0        + bv.x;
                o.y = Aj[c]     + bv.y;
                o.z = Aj[c + 1] + bv.z;
                o.w = Aj[c + 2] + bv.w;
                *(float4*)&gr[c] = o;
            }
        }
    }
}

// ---------------- 5b) y-pass + max/argmax (R11 version) ----------------------
__global__ void maxarg_kernel(float* __restrict__ outS) {
    int b = blockIdx.y, lq = blockIdx.x;
    int yq = lq / H3;
    const float4* Gb4 = (const float4*)(g_G + (size_t)b * L3 * L3);
    const float4* z4p = (const float4*)g_zero;

    const float4* rb[3];
    bool qv[3];
    #pragma unroll
    for (int t = 0; t < 3; t++) {
        int di = t - 1;
        qv[t] = ((unsigned)(yq + di) < H3);
        rb[t] = qv[t] ? (Gb4 + (size_t)(lq + 48 * di) * 576 + 12 * di) : z4p;
    }
    const float4* rnk4 = (const float4*)&g_nrm[1][b * L3];

    float best = -1e30f; int bi = 0;
    for (int gi = threadIdx.x; gi < 576; gi += 256) {
        int yk = gi / 12;
        bool k0 = qv[0] && (yk >= 1);
        bool k2 = qv[2] && (yk <= H3 - 2);
        float4 v0 = k0 ? rb[0][gi] : *z4p;
        float4 v1 = qv[1] ? rb[1][gi] : *z4p;
        float4 v2 = k2 ? rb[2][gi] : *z4p;
        float4 rk = rnk4[gi];
        float s0 = (v0.x + v1.x + v2.x) * rk.x;
        float s1 = (v0.y + v1.y + v2.y) * rk.y;
        float s2 = (v0.z + v1.z + v2.z) * rk.z;
        float s3 = (v0.w + v1.w + v2.w) * rk.w;
        int lk = gi * 4;
        if (s0 > best) { best = s0; bi = lk; }
        if (s1 > best) { best = s1; bi = lk + 1; }
        if (s2 > best) { best = s2; bi = lk + 2; }
        if (s3 > best) { best = s3; bi = lk + 3; }
    }

    __shared__ float sv[256];
    __shared__ int   si[256];
    sv[threadIdx.x] = best; si[threadIdx.x] = bi;
    __syncthreads();
    for (int st = 128; st > 0; st >>= 1) {
        if (threadIdx.x < st) {
            float o = sv[threadIdx.x + st]; int oi = si[threadIdx.x + st];
            if (o > sv[threadIdx.x] || (o == sv[threadIdx.x] && oi < si[threadIdx.x])) {
                sv[threadIdx.x] = o; si[threadIdx.x] = oi;
            }
        }
        __syncthreads();
    }
    if (threadIdx.x == 0) {
        g_idx[b * L3 + lq] = si[0];
        outS[b * L3 + lq]  = sv[0] / g_nrm[0][b * L3 + lq];
    }
}

// ---------------- 6) merged gather + fold-normalize (all 3 levels) -----------
__global__ void __launch_bounds__(256) transfer_kernel(float* __restrict__ outT3,
                                                       float* __restrict__ outT2,
                                                       float* __restrict__ outT1) {
    __shared__ __align__(16) float acc[3456];    // xpc*(C+8) <= 3456 floats
    __shared__ __align__(16) int4 ent[3][14];    // {dxs, base4, ok, pad}
    __shared__ float sinv[12];
    int j = blockIdx.x;
    int tid = threadIdx.x;

    // segment decode
    const float* clT; float* out; int C, W, ls, xpc, b, y, zc;
    if (j < XB3) {
        clT = g_cl3T; out = outT3; C = C3; W = H3; ls = 0; xpc = 12;
        y = j % H3; b = (j / H3) & 3; zc = j / (H3 * 4);
    } else if (j < XB3 + XB2) {
        int q = j - XB3;
        clT = g_cl2T; out = outT2; C = C2; W = H2; ls = 1; xpc = 24;
        y = q % H2; b = (q / H2) & 3; zc = q / (H2 * 4);
    } else {
        int q = j - XB3 - XB2;
        clT = g_cl1T; out = outT1; C = C1; W = H1; ls = 2; xpc = 48;
        y = q % H1; b = (q / H1) & 3; zc = q / (H1 * 4);
    }
    int xlo = zc * xpc;
    int cpg  = C >> 2;
    int cg   = tid & (cpg - 1);
    int xsub = tid / cpg;
    int ppp  = 256 / cpg;
    int astr = C + 8;

    int tyq  = y >> ls;
    int txq0 = xlo >> ls;
    const int* idxb = g_idx + b * L3;

    if (tid < 42) {
        int a = tid / 14, xi = tid % 14;
        int xq = txq0 - 1 + xi;
        int yq = tyq - 1 + a;
        int dxs = 0, base4 = 0, ok = 0;
        if ((unsigned)xq < H3 && (unsigned)yq < H3) {
            int idx = idxb[yq * H3 + xq];
            int yk = idx / H3, xk = idx % H3;
            int ys = y + ((yk - yq) << ls);
            if ((unsigned)ys < (unsigned)W) {
                ok = 1;
                base4 = ys * W * (C >> 2);
            }
            dxs = (xk - xq) << ls;
        }
        ent[a][xi] = make_int4(dxs, base4, ok, 0);
    }
    if (tid < 12) {
        int txq = txq0 + tid;
        int nvx = 1 + (txq > 0) + (txq < H3 - 1);
        int nvy = 1 + (tyq > 0) + (tyq < H3 - 1);
        sinv[tid] = 1.0f / (float)(nvx * nvy);
    }
    __syncthreads();

    const float4* f4b = (const float4*)(clT + (size_t)b * W * W * C);

    for (int xo = 0; xo < xpc; xo += ppp) {
        int x = xlo + xo + xsub;
        int xib = (x >> ls) - txq0;
        float4 sum = make_float4(0.f, 0.f, 0.f, 0.f);
        #pragma unroll
        for (int a = 0; a < 3; a++) {
            #pragma unroll
            for (int dx = 0; dx < 3; dx++) {
                int4 e = ent[a][xib + dx];
                int xs = x + e.x;
                if (e.z && (unsigned)xs < (unsigned)W) {
                    float4 v = f4b[e.y + xs * cpg + cg];
                    sum.x += v.x; sum.y += v.y; sum.z += v.z; sum.w += v.w;
                }
            }
        }
        float ic = sinv[xib];
        *(float4*)&acc[(xo + xsub) * astr + cg * 4] =
            make_float4(sum.x * ic, sum.y * ic, sum.z * ic, sum.w * ic);
    }
    __syncthreads();

    size_t ob = (size_t)b * C * W * W + (size_t)y * W + xlo;
    int tot = C * xpc;                           // == 3072 for all segments
    for (int i = tid; i < tot; i += 256) {
        int c = i / xpc, x = i % xpc;
        out[ob + (size_t)c * W * W + x] = acc[x * astr + c];
    }
}

// ---------------- launch ------------------------------------------------------
extern "C" void kernel_launch(void* const* d_in, const int* in_sizes, int n_in,
                              void* d_out, int out_size) {
    const float* img = (const float*)d_in[0];   // dh_img_lv3 [4,256,48,48]
    const float* ref = (const float*)d_in[1];   // dh_ref_lv3 [4,256,48,48]
    const float* cl1 = (const float*)d_in[2];   // cl_ref_lv1 [4,64,192,192]
    const float* cl2 = (const float*)d_in[3];   // cl_ref_lv2 [4,128,96,96]
    const float* cl3 = (const float*)d_in[4];   // cl_ref_lv3 [4,256,48,48]

    float* outS  = (float*)d_out;               // [4,1,48,48]
    float* outT3 = outS  + BB * L3;             // [4,256,48,48]
    float* outT2 = outT3 + (size_t)BB * C3 * L3;    // [4,128,96,96]
    float* outT1 = outT2 + (size_t)BB * C2 * L2n;   // [4,64,192,192]

    cudaFuncSetAttribute(gemm_kernel,
                         cudaFuncAttributeMaxDynamicSharedMemorySize, GEMM_SMEM);

    // 0: GEMM (triggers PDL dependents at start)
    gemm_kernel<<<dim3(L3 / 128, L3 / 128, BB), 256, GEMM_SMEM>>>(img, ref);

    // 1: side work (transposes + norms), PDL so it fills gemm's gaps/tail
    {
        cudaLaunchConfig_t cfg = {};
        cfg.gridDim = dim3(NSIDE);
        cfg.blockDim = dim3(256);
        cfg.dynamicSmemBytes = 0;
        cfg.stream = 0;
        cudaLaunchAttribute at;
        at.id = cudaLaunchAttributeProgrammaticStreamSerialization;
        at.val.programmaticStreamSerializationAllowed = 1;
        cfg.attrs = &at;
        cfg.numAttrs = 1;
        cudaError_t e = cudaLaunchKernelEx(&cfg, side_kernel, img, ref, cl1, cl2, cl3);
        if (e != cudaSuccess) {
            side_kernel<<<NSIDE, 256>>>(img, ref, cl1, cl2, cl3);
        }
    }

    // 2: x-pass (normal launch: full barrier on gemm + side)
    gpass1_kernel<<<dim3(L3 / 4, BB), 256>>>();

    // 3: y-pass + argmax (profiled slot)
    maxarg_kernel<<<dim3(L3, BB), 256>>>(outS);

    // 4: all three transfers in one launch
    transfer_kernel<<<NXFER, 256>>>(outT3, outT2, outT1);
}

// round 14
// speedup vs baseline: 1.1218x; 1.0167x over previous
#include <cuda_runtime.h>
#include <cstdint>

// Problem constants
#define BB   4
#define C3   256
#define H3   48
#define L3   (H3*H3)          // 2304
#define C2   128
#define H2   96
#define L2n  (H2*H2)          // 9216
#define C1   64
#define H1   192
#define L1n  (H1*H1)          // 36864
#define EPSN 1e-12f

#define BK2 32
#define GEMM_SMEM (2 * BK2 * 128 * 2 * 4)      // 65536 bytes

// side_kernel block counts
#define NSQB 72                                 // 9 tiles x 2 tensors x 4 batches
#define NT3  2304
#define NT2  4608
#define NT1  9216
#define NSIDE (NSQB + NT3 + NT2 + NT1)          // 16200

// merged transfer block counts
#define XB3 768                                 // 48*4*4
#define XB2 1536                                // 96*4*4
#define XB1 3072                                // 192*4*4
#define NXFER (XB3 + XB2 + XB1)                 // 5376

// ---------------- scratch (static device globals; no allocation) -------------
__device__ __align__(16) float g_P[(size_t)BB * L3 * L3];   // [b][lq][lk]  ~85MB
__device__ __align__(16) float g_G[(size_t)BB * L3 * L3];   // x-pass of shifted sum
__device__ __align__(16) float g_cl3T[(size_t)BB * L3 * C3];  // [b][pix][c]
__device__ __align__(16) float g_cl2T[(size_t)BB * L2n * C2];
__device__ __align__(16) float g_cl1T[(size_t)BB * L1n * C1];
__device__ __align__(16) float g_nrm[2][BB * L3];     // 0: nq(img) norm, 1: 1/nk(ref)
__device__ int   g_idx[BB * L3];                      // argmax index per query
__device__ __align__(16) float g_zero[16];            // stays zero (never written)

// ---------------- helpers -----------------------------------------------------
__device__ __forceinline__ void cp_async16(uint32_t smem, const void* gmem) {
    asm volatile("cp.async.cg.shared.global [%0], [%1], 16;\n" :: "r"(smem), "l"(gmem));
}
__device__ __forceinline__ void cp_commit() {
    asm volatile("cp.async.commit_group;\n" ::: "memory");
}
__device__ __forceinline__ void cp_wait0() {
    asm volatile("cp.async.wait_group 0;\n" ::: "memory");
}
// packed fp32x2 FMA: d = a*b + d  (componentwise, exact fp32 semantics)
__device__ __forceinline__ void fma2(unsigned long long& d, unsigned long long a,
                                     unsigned long long b) {
    asm("fma.rn.f32x2 %0, %1, %2, %0;" : "+l"(d) : "l"(a), "l"(b));
}
__device__ __forceinline__ unsigned long long bcast2(float x) {
    unsigned long long r;
    asm("mov.b64 %0, {%1, %1};" : "=l"(r) : "f"(x));
    return r;
}
__device__ __forceinline__ void pdl_launch_dependents() {
    asm volatile("griddepcontrol.launch_dependents;" ::: "memory");
}
__device__ __forceinline__ void pdl_wait() {
    asm volatile("griddepcontrol.wait;" ::: "memory");
}

// ---------------- side kernel: 3 transposes + fused sqsum/boxnorm ------------
__global__ void __launch_bounds__(256) side_kernel(const float* __restrict__ img,
                                                   const float* __restrict__ ref,
                                                   const float* __restrict__ cl1,
                                                   const float* __restrict__ cl2,
                                                   const float* __restrict__ cl3) {
    __shared__ float sbuf[1056];                 // transpose 32x33; sqsumbox uses 324
    int j = blockIdx.x;
    int tid = threadIdx.x;

    if (j < NSQB) {
        // ---- fused per-pixel sqnorm + 3x3 box-sum -> patch norm ----
        int tile = j % 9, which = (j / 9) & 1, b = j / 18;
        const float* src = ((which == 0) ? img : ref) + (size_t)b * C3 * L3;
        int ty0 = (tile / 3) * 16, tx0 = (tile % 3) * 16;
        for (int p = tid; p < 324; p += 256) {
            int py = ty0 + p / 18 - 1, px = tx0 + p % 18 - 1;
            float s = 0.f;
            if ((unsigned)py < H3 && (unsigned)px < H3) {
                const float* sp = src + py * H3 + px;
                #pragma unroll 4
                for (int c = 0; c < C3; c++) {
                    float v = sp[(size_t)c * L3];
                    s += v * v;
                }
            }
            sbuf[p] = s;
        }
        __syncthreads();
        {
            int py = tid / 16, px = tid % 16;       // all 256 threads
            float acc = 0.f;
            #pragma unroll
            for (int dy = 0; dy < 3; dy++)
                #pragma unroll
                for (int dx = 0; dx < 3; dx++)
                    acc += sbuf[(py + dy) * 18 + px + dx];
            float n = fmaxf(sqrtf(acc), EPSN);
            g_nrm[which][b * L3 + (ty0 + py) * H3 + tx0 + px] = which ? (1.0f / n) : n;
        }
        return;
    }

    // ---- transpose cl -> channel-last ----
    int q = j - NSQB;
    const float* src; float* dst; int C, L;
    if (q < NT3)            { src = cl3; dst = g_cl3T; C = C3; L = L3; }
    else if (q < NT3 + NT2) { q -= NT3;  src = cl2; dst = g_cl2T; C = C2; L = L2n; }
    else                    { q -= NT3 + NT2; src = cl1; dst = g_cl1T; C = C1; L = L1n; }
    int nl = L / 32, nc = C / 32;
    int l0 = (q % nl) * 32, c0 = ((q / nl) % nc) * 32, b = q / (nl * nc);
    const float* s = src + (size_t)b * C * L;
    float* d = dst + (size_t)b * L * C;
    int txx = tid % 32, tyy = tid / 32;
    #pragma unroll
    for (int i = tyy; i < 32; i += 8)
        sbuf[i * 33 + txx] = s[(size_t)(c0 + i) * L + l0 + txx];
    __syncthreads();
    #pragma unroll
    for (int i = tyy; i < 32; i += 8)
        d[(size_t)(l0 + i) * C + c0 + txx] = sbuf[txx * 33 + i];
}

// ---------------- 4) SGEMM via packed FFMA2, 16m x 4n packed-m microtile -----
// acc pairs come straight from A LDS.128 (m-consecutive); only B needs bcast.
__global__ void __launch_bounds__(256, 2) gemm_kernel(const float* __restrict__ img,
                                                      const float* __restrict__ ref) {
    // release PDL dependents immediately: side_kernel may co-schedule
    pdl_launch_dependents();

    extern __shared__ __align__(16) float sm[];
    const int b  = blockIdx.z;
    const int m0 = blockIdx.y * 128;
    const int n0 = blockIdx.x * 128;
    const float* A  = img + (size_t)b * C3 * L3;   // [k][m]
    const float* Bm = ref + (size_t)b * C3 * L3;   // [k][n]
    float* Cc = g_P + (size_t)b * L3 * L3;

    const int tid = threadIdx.x;
    const int lr  = tid >> 5;            // 0..7  (cp.async row)
    const int lc  = (tid & 31) * 4;      // cp.async col
    const int tx  = tid & 31;            // n group (lane)
    const int ty  = tid >> 5;            // m group (= warp id)

    const float* gA[4]; const float* gB[4];
    uint32_t sA[2][4], sB[2][4];
    #pragma unroll
    for (int i = 0; i < 4; i++) {
        gA[i] = &A [(size_t)(lr + 8 * i) * L3 + m0 + lc];
        gB[i] = &Bm[(size_t)(lr + 8 * i) * L3 + n0 + lc];
        #pragma unroll
        for (int u = 0; u < 2; u++) {
            sA[u][i] = (uint32_t)__cvta_generic_to_shared(
                &sm[u * 4096 + (lr + 8 * i) * 128 + lc]);
            sB[u][i] = (uint32_t)__cvta_generic_to_shared(
                &sm[8192 + u * 4096 + (lr + 8 * i) * 128 + lc]);
        }
    }
    const size_t kstep = (size_t)BK2 * L3;

    unsigned long long acc2[8][4];       // [m-pair][n]
    #pragma unroll
    for (int i = 0; i < 8; i++)
        #pragma unroll
        for (int j = 0; j < 4; j++) acc2[i][j] = 0ULL;

    #pragma unroll
    for (int i = 0; i < 4; i++) { cp_async16(sA[0][i], gA[i]); cp_async16(sB[0][i], gB[i]); }
    cp_commit();

    int buf = 0;
    for (int ks = 0; ks < C3 / BK2; ks++) {
        cp_wait0();
        __syncthreads();

        if (ks + 1 < C3 / BK2) {
            size_t off = (size_t)(ks + 1) * kstep;
            int nb = buf ^ 1;
            #pragma unroll
            for (int i = 0; i < 4; i++) {
                cp_async16(sA[nb][i], gA[i] + off);
                cp_async16(sB[nb][i], gB[i] + off);
            }
            cp_commit();
        }

        const float* Ab = &sm[buf * 4096];
        const float* Bb = &sm[8192 + buf * 4096];
        #pragma unroll 8
        for (int kk = 0; kk < BK2; kk++) {
            const float* Arow = &Ab[kk * 128 + ty * 16];
            float4 t0 = *(const float4*)(Arow);
            float4 t1 = *(const float4*)(Arow + 4);
            float4 t2 = *(const float4*)(Arow + 8);
            float4 t3 = *(const float4*)(Arow + 12);
            unsigned long long ap[8];
            ap[0] = ((unsigned long long*)&t0)[0]; ap[1] = ((unsigned long long*)&t0)[1];
            ap[2] = ((unsigned long long*)&t1)[0]; ap[3] = ((unsigned long long*)&t1)[1];
            ap[4] = ((unsigned long long*)&t2)[0]; ap[5] = ((unsigned long long*)&t2)[1];
            ap[6] = ((unsigned long long*)&t3)[0]; ap[7] = ((unsigned long long*)&t3)[1];
            float4 bv = *(const float4*)&Bb[kk * 128 + tx * 4];
            unsigned long long bb[4];
            bb[0] = bcast2(bv.x); bb[1] = bcast2(bv.y);
            bb[2] = bcast2(bv.z); bb[3] = bcast2(bv.w);
            #pragma unroll
            for (int p = 0; p < 8; p++) {
                fma2(acc2[p][0], ap[p], bb[0]);
                fma2(acc2[p][1], ap[p], bb[1]);
                fma2(acc2[p][2], ap[p], bb[2]);
                fma2(acc2[p][3], ap[p], bb[3]);
            }
        }
        buf ^= 1;
    }

    // epilogue: unpack pairs -> two float4 row stores per pair
    #pragma unroll
    for (int p = 0; p < 8; p++) {
        int m = m0 + ty * 16 + p * 2;
        float2 f0 = *(float2*)&acc2[p][0];
        float2 f1 = *(float2*)&acc2[p][1];
        float2 f2 = *(float2*)&acc2[p][2];
        float2 f3 = *(float2*)&acc2[p][3];
        float4 r0 = make_float4(f0.x, f1.x, f2.x, f3.x);   // row m
        float4 r1 = make_float4(f0.y, f1.y, f2.y, f3.y);   // row m+1
        *(float4*)&Cc[(size_t)m * L3 + n0 + tx * 4]       = r0;
        *(float4*)&Cc[(size_t)(m + 1) * L3 + n0 + tx * 4] = r1;
    }
}

// ---------------- 5a) x-pass: G[r][c] = A[c-1] + B[c] + C[c+1], 4 rows/block -
#define SRS 2312
__global__ void gpass1_kernel() {
    __shared__ __align__(16) float sR[6 * SRS];
    int r0 = blockIdx.x * 4, b = blockIdx.y;
    const float* Pb = g_P + (size_t)b * L3 * L3;
    float* Gb = g_G + (size_t)b * L3 * L3;
    int tid = threadIdx.x;

    #pragma unroll
    for (int i = 0; i < 6; i++) {
        int rr = min(max(r0 - 1 + i, 0), L3 - 1);   // clamped rows never used
        const float4* src = (const float4*)(Pb + (size_t)rr * L3);
        float4* dst = (float4*)&sR[i * SRS + 4];
        for (int g = tid; g < 576; g += 256) dst[g] = src[g];
    }
    __syncthreads();

    #pragma unroll
    for (int j = 0; j < 4; j++) {
        int r = r0 + j;
        int xq = r % H3;
        const float* Aj = &sR[j * SRS + 4];
        const float* Bj = &sR[(j + 1) * SRS + 4];
        const float* Cj = &sR[(j + 2) * SRS + 4];
        float* gr = Gb + (size_t)r * L3;
        bool hasA = (xq != 0), hasC = (xq != H3 - 1);

        if (hasA && hasC) {
            for (int g = tid; g < 576; g += 256) {
                int c = g * 4;
                int m = (g % 12) * 4;
                float4 bv = *(const float4*)&Bj[c];
                float a0 = (m != 0) ? Aj[c - 1] : 0.f;
                float c3 = (m != 44) ? Cj[c + 4] : 0.f;
                float4 o;
                o.x = a0        + bv.x + Cj[c + 1];
                o.y = Aj[c]     + bv.y + Cj[c + 2];
                o.z = Aj[c + 1] + bv.z + Cj[c + 3];
                o.w = Aj[c + 2] + bv.w + c3;
                *(float4*)&gr[c] = o;
            }
        } else if (!hasA) {
            for (int g = tid; g < 576; g += 256) {
                int c = g * 4;
                int m = (g % 12) * 4;
                float4 bv = *(const float4*)&Bj[c];
                float c3 = (m != 44) ? Cj[c + 4] : 0.f;
                float4 o;
                o.x = bv.x + Cj[c + 1];
                o.y = bv.y + Cj[c + 2];
                o.z = bv.z + Cj[c + 3];
                o.w = bv.w + c3;
                *(float4*)&gr[c] = o;
            }
        } else {
            for (int g = tid; g < 576; g += 256) {
                int c = g * 4;
                int m = (g % 12) * 4;
                float4 bv = *(const float4*)&Bj[c];
                float a0 = (m != 0) ? Aj[c - 1] : 0.f;
                float4 o;
                o.x = a0        + bv.x;
                o.y = Aj[c]     + bv.y;
                o.z = Aj[c + 1] + bv.z;
                o.w = Aj[c + 2] + bv.w;
                *(float4*)&gr[c] = o;
            }
        }
    }
    pdl_launch_dependents();
}

// ---------------- 5b) y-pass + max/argmax ------------------------------------
__global__ void maxarg_kernel(float* __restrict__ outS) {
    int b = blockIdx.y, lq = blockIdx.x;
    int yq = lq / H3;
    const float4* Gb4 = (const float4*)(g_G + (size_t)b * L3 * L3);
    const float4* z4p = (const float4*)g_zero;

    const float4* rb[3];
    bool qv[3];
    #pragma unroll
    for (int t = 0; t < 3; t++) {
        int di = t - 1;
        qv[t] = ((unsigned)(yq + di) < H3);
        rb[t] = qv[t] ? (Gb4 + (size_t)(lq + 48 * di) * 576 + 12 * di) : z4p;
    }
    const float4* rnk4 = (const float4*)&g_nrm[1][b * L3];

    pdl_wait();     // g_G from gpass1 must be visible before loads

    float best = -1e30f; int bi = 0;
    for (int gi = threadIdx.x; gi < 576; gi += 256) {
        int yk = gi / 12;
        bool k0 = qv[0] && (yk >= 1);
        bool k2 = qv[2] && (yk <= H3 - 2);
        float4 v0 = k0 ? rb[0][gi] : *z4p;
        float4 v1 = qv[1] ? rb[1][gi] : *z4p;
        float4 v2 = k2 ? rb[2][gi] : *z4p;
        float4 rk = rnk4[gi];
        float s0 = (v0.x + v1.x + v2.x) * rk.x;
        float s1 = (v0.y + v1.y + v2.y) * rk.y;
        float s2 = (v0.z + v1.z + v2.z) * rk.z;
        float s3 = (v0.w + v1.w + v2.w) * rk.w;
        int lk = gi * 4;
        if (s0 > best) { best = s0; bi = lk; }
        if (s1 > best) { best = s1; bi = lk + 1; }
        if (s2 > best) { best = s2; bi = lk + 2; }
        if (s3 > best) { best = s3; bi = lk + 3; }
    }

    __shared__ float sv[256];
    __shared__ int   si[256];
    sv[threadIdx.x] = best; si[threadIdx.x] = bi;
    __syncthreads();
    for (int st = 128; st > 0; st >>= 1) {
        if (threadIdx.x < st) {
            float o = sv[threadIdx.x + st]; int oi = si[threadIdx.x + st];
            if (o > sv[threadIdx.x] || (o == sv[threadIdx.x] && oi < si[threadIdx.x])) {
                sv[threadIdx.x] = o; si[threadIdx.x] = oi;
            }
        }
        __syncthreads();
    }
    if (threadIdx.x == 0) {
        g_idx[b * L3 + lq] = si[0];
        outS[b * L3 + lq]  = sv[0] / g_nrm[0][b * L3 + lq];
    }
    pdl_launch_dependents();
}

// ---------------- 6) merged gather + fold-normalize (all 3 levels) -----------
__global__ void __launch_bounds__(256) transfer_kernel(float* __restrict__ outT3,
                                                       float* __restrict__ outT2,
                                                       float* __restrict__ outT1) {
    __shared__ __align__(16) float acc[3456];    // xpc*(C+8) <= 3456 floats
    __shared__ __align__(16) int4 ent[3][14];    // {dxs, base4, ok, pad}
    __shared__ float sinv[12];
    int j = blockIdx.x;
    int tid = threadIdx.x;

    // segment decode
    const float* clT; float* out; int C, W, ls, xpc, b, y, zc;
    if (j < XB3) {
        clT = g_cl3T; out = outT3; C = C3; W = H3; ls = 0; xpc = 12;
        y = j % H3; b = (j / H3) & 3; zc = j / (H3 * 4);
    } else if (j < XB3 + XB2) {
        int q = j - XB3;
        clT = g_cl2T; out = outT2; C = C2; W = H2; ls = 1; xpc = 24;
        y = q % H2; b = (q / H2) & 3; zc = q / (H2 * 4);
    } else {
        int q = j - XB3 - XB2;
        clT = g_cl1T; out = outT1; C = C1; W = H1; ls = 2; xpc = 48;
        y = q % H1; b = (q / H1) & 3; zc = q / (H1 * 4);
    }
    int xlo = zc * xpc;
    int cpg  = C >> 2;
    int cg   = tid & (cpg - 1);
    int xsub = tid / cpg;
    int ppp  = 256 / cpg;
    int astr = C + 8;

    int tyq  = y >> ls;
    int txq0 = xlo >> ls;
    const int* idxb = g_idx + b * L3;

    pdl_wait();     // g_idx from maxarg must be visible

    if (tid < 42) {
        int a = tid / 14, xi = tid % 14;
        int xq = txq0 - 1 + xi;
        int yq = tyq - 1 + a;
        int dxs = 0, base4 = 0, ok = 0;
        if ((unsigned)xq < H3 && (unsigned)yq < H3) {
            int idx = idxb[yq * H3 + xq];
            int yk = idx / H3, xk = idx % H3;
            int ys = y + ((yk - yq) << ls);
            if ((unsigned)ys < (unsigned)W) {
                ok = 1;
                base4 = ys * W * (C >> 2);
            }
            dxs = (xk - xq) << ls;
        }
        ent[a][xi] = make_int4(dxs, base4, ok, 0);
    }
    if (tid < 12) {
        int txq = txq0 + tid;
        int nvx = 1 + (txq > 0) + (txq < H3 - 1);
        int nvy = 1 + (tyq > 0) + (tyq < H3 - 1);
        sinv[tid] = 1.0f / (float)(nvx * nvy);
    }
    __syncthreads();

    const float4* f4b = (const float4*)(clT + (size_t)b * W * W * C);

    for (int xo = 0; xo < xpc; xo += ppp) {
        int x = xlo + xo + xsub;
        int xib = (x >> ls) - txq0;
        float4 sum = make_float4(0.f, 0.f, 0.f, 0.f);
        #pragma unroll
        for (int a = 0; a < 3; a++) {
            #pragma unroll
            for (int dx = 0; dx < 3; dx++) {
                int4 e = ent[a][xib + dx];
                int xs = x + e.x;
                if (e.z && (unsigned)xs < (unsigned)W) {
                    float4 v = f4b[e.y + xs * cpg + cg];
                    sum.x += v.x; sum.y += v.y; sum.z += v.z; sum.w += v.w;
                }
            }
        }
        float ic = sinv[xib];
        *(float4*)&acc[(xo + xsub) * astr + cg * 4] =
            make_float4(sum.x * ic, sum.y * ic, sum.z * ic, sum.w * ic);
    }
    __syncthreads();

    size_t ob = (size_t)b * C * W * W + (size_t)y * W + xlo;
    int tot = C * xpc;                           // == 3072 for all segments
    for (int i = tid; i < tot; i += 256) {
        int c = i / xpc, x = i % xpc;
        out[ob + (size_t)c * W * W + x] = acc[x * astr + c];
    }
}

// ---------------- launch ------------------------------------------------------
static void launch_pdl(void* func, dim3 grid, dim3 block, void** args) {
    cudaLaunchConfig_t cfg = {};
    cfg.gridDim = grid;
    cfg.blockDim = block;
    cfg.dynamicSmemBytes = 0;
    cfg.stream = 0;
    cudaLaunchAttribute at;
    at.id = cudaLaunchAttributeProgrammaticStreamSerialization;
    at.val.programmaticStreamSerializationAllowed = 1;
    cfg.attrs = &at;
    cfg.numAttrs = 1;
    cudaLaunchKernelExC(&cfg, func, args);
}

extern "C" void kernel_launch(void* const* d_in, const int* in_sizes, int n_in,
                              void* d_out, int out_size) {
    const float* img = (const float*)d_in[0];   // dh_img_lv3 [4,256,48,48]
    const float* ref = (const float*)d_in[1];   // dh_ref_lv3 [4,256,48,48]
    const float* cl1 = (const float*)d_in[2];   // cl_ref_lv1 [4,64,192,192]
    const float* cl2 = (const float*)d_in[3];   // cl_ref_lv2 [4,128,96,96]
    const float* cl3 = (const float*)d_in[4];   // cl_ref_lv3 [4,256,48,48]

    float* outS  = (float*)d_out;               // [4,1,48,48]
    float* outT3 = outS  + BB * L3;             // [4,256,48,48]
    float* outT2 = outT3 + (size_t)BB * C3 * L3;    // [4,128,96,96]
    float* outT1 = outT2 + (size_t)BB * C2 * L2n;   // [4,64,192,192]

    cudaFuncSetAttribute(gemm_kernel,
                         cudaFuncAttributeMaxDynamicSharedMemorySize, GEMM_SMEM);

    // 0: GEMM (triggers PDL dependents at start)
    gemm_kernel<<<dim3(L3 / 128, L3 / 128, BB), 256, GEMM_SMEM>>>(img, ref);

    // 1: side work (transposes + norms), PDL so it fills gemm's gaps/tail
    {
        void* args[] = { (void*)&img, (void*)&ref, (void*)&cl1, (void*)&cl2, (void*)&cl3 };
        launch_pdl((void*)side_kernel, dim3(NSIDE), dim3(256), args);
    }

    // 2: x-pass (normal launch: full barrier on gemm + side)
    gpass1_kernel<<<dim3(L3 / 4, BB), 256>>>();

    // 3: y-pass + argmax (PDL after gpass1)
    {
        void* args[] = { (void*)&outS };
        launch_pdl((void*)maxarg_kernel, dim3(L3, BB), dim3(256), args);
    }

    // 4: all three transfers in one launch (PDL after maxarg)
    {
        void* args[] = { (void*)&outT3, (void*)&outT2, (void*)&outT1 };
        launch_pdl((void*)transfer_kernel, dim3(NXFER), dim3(256), args);
    }
}

// round 15
// speedup vs baseline: 1.1278x; 1.0054x over previous
#include <cuda_runtime.h>
#include <cstdint>

// Problem constants
#define BB   4
#define C3   256
#define H3   48
#define L3   (H3*H3)          // 2304
#define C2   128
#define H2   96
#define L2n  (H2*H2)          // 9216
#define C1   64
#define H1   192
#define L1n  (H1*H1)          // 36864
#define EPSN 1e-12f

#define BK2 32
#define GEMM_SMEM (2 * BK2 * 128 * 2 * 4)      // 65536 bytes

// side_kernel block counts
#define NSQB 72                                 // 9 tiles x 2 tensors x 4 batches
#define NT3  2304
#define NT2  4608
#define NT1  9216
#define NSIDE (NSQB + NT3 + NT2 + NT1)          // 16200

// merged transfer block counts
#define XB3 768                                 // 48*4*4
#define XB2 1536                                // 96*4*4
#define XB1 3072                                // 192*4*4
#define NXFER (XB3 + XB2 + XB1)                 // 5376

// ---------------- scratch (static device globals; no allocation) -------------
__device__ __align__(16) float g_P[(size_t)BB * L3 * L3];   // [b][lq][lk]  ~85MB
__device__ __align__(16) float g_G[(size_t)BB * L3 * L3];   // x-pass of shifted sum
__device__ __align__(16) float g_cl3T[(size_t)BB * L3 * C3];  // [b][pix][c]
__device__ __align__(16) float g_cl2T[(size_t)BB * L2n * C2];
__device__ __align__(16) float g_cl1T[(size_t)BB * L1n * C1];
__device__ __align__(16) float g_nrm[2][BB * L3];     // 0: nq(img) norm, 1: 1/nk(ref)
__device__ int   g_idx[BB * L3];                      // argmax index per query
__device__ __align__(16) float g_zero[16];            // stays zero (never written)

// ---------------- helpers -----------------------------------------------------
__device__ __forceinline__ void cp_async16(uint32_t smem, const void* gmem) {
    asm volatile("cp.async.cg.shared.global [%0], [%1], 16;\n" :: "r"(smem), "l"(gmem));
}
__device__ __forceinline__ void cp_commit() {
    asm volatile("cp.async.commit_group;\n" ::: "memory");
}
__device__ __forceinline__ void cp_wait0() {
    asm volatile("cp.async.wait_group 0;\n" ::: "memory");
}
// packed fp32x2 FMA: d = a*b + d  (componentwise, exact fp32 semantics)
__device__ __forceinline__ void fma2(unsigned long long& d, unsigned long long a,
                                     unsigned long long b) {
    asm("fma.rn.f32x2 %0, %1, %2, %0;" : "+l"(d) : "l"(a), "l"(b));
}
__device__ __forceinline__ unsigned long long bcast2(float x) {
    unsigned long long r;
    asm("mov.b64 %0, {%1, %1};" : "=l"(r) : "f"(x));
    return r;
}
__device__ __forceinline__ void pdl_launch_dependents() {
    asm volatile("griddepcontrol.launch_dependents;" ::: "memory");
}
__device__ __forceinline__ void pdl_wait() {
    asm volatile("griddepcontrol.wait;" ::: "memory");
}

// ---------------- side kernel: 3 transposes + fused sqsum/boxnorm ------------
__global__ void __launch_bounds__(256) side_kernel(const float* __restrict__ img,
                                                   const float* __restrict__ ref,
                                                   const float* __restrict__ cl1,
                                                   const float* __restrict__ cl2,
                                                   const float* __restrict__ cl3) {
    __shared__ float sbuf[1056];                 // transpose 32x33; sqsumbox uses 324
    int j = blockIdx.x;
    int tid = threadIdx.x;

    if (j < NSQB) {
        // ---- fused per-pixel sqnorm + 3x3 box-sum -> patch norm ----
        int tile = j % 9, which = (j / 9) & 1, b = j / 18;
        const float* src = ((which == 0) ? img : ref) + (size_t)b * C3 * L3;
        int ty0 = (tile / 3) * 16, tx0 = (tile % 3) * 16;
        for (int p = tid; p < 324; p += 256) {
            int py = ty0 + p / 18 - 1, px = tx0 + p % 18 - 1;
            float s = 0.f;
            if ((unsigned)py < H3 && (unsigned)px < H3) {
                const float* sp = src + py * H3 + px;
                #pragma unroll 4
                for (int c = 0; c < C3; c++) {
                    float v = sp[(size_t)c * L3];
                    s += v * v;
                }
            }
            sbuf[p] = s;
        }
        __syncthreads();
        {
            int py = tid / 16, px = tid % 16;       // all 256 threads
            float acc = 0.f;
            #pragma unroll
            for (int dy = 0; dy < 3; dy++)
                #pragma unroll
                for (int dx = 0; dx < 3; dx++)
                    acc += sbuf[(py + dy) * 18 + px + dx];
            float n = fmaxf(sqrtf(acc), EPSN);
            g_nrm[which][b * L3 + (ty0 + py) * H3 + tx0 + px] = which ? (1.0f / n) : n;
        }
        return;
    }

    // ---- transpose cl -> channel-last ----
    int q = j - NSQB;
    const float* src; float* dst; int C, L;
    if (q < NT3)            { src = cl3; dst = g_cl3T; C = C3; L = L3; }
    else if (q < NT3 + NT2) { q -= NT3;  src = cl2; dst = g_cl2T; C = C2; L = L2n; }
    else                    { q -= NT3 + NT2; src = cl1; dst = g_cl1T; C = C1; L = L1n; }
    int nl = L / 32, nc = C / 32;
    int l0 = (q % nl) * 32, c0 = ((q / nl) % nc) * 32, b = q / (nl * nc);
    const float* s = src + (size_t)b * C * L;
    float* d = dst + (size_t)b * L * C;
    int txx = tid % 32, tyy = tid / 32;
    #pragma unroll
    for (int i = tyy; i < 32; i += 8)
        sbuf[i * 33 + txx] = s[(size_t)(c0 + i) * L + l0 + txx];
    __syncthreads();
    #pragma unroll
    for (int i = tyy; i < 32; i += 8)
        d[(size_t)(l0 + i) * C + c0 + txx] = sbuf[txx * 33 + i];
}

// ---------------- 4) SGEMM via packed FFMA2, 16m x 4n packed-m microtile -----
__global__ void __launch_bounds__(256, 2) gemm_kernel(const float* __restrict__ img,
                                                      const float* __restrict__ ref) {
    // release PDL dependents immediately: side_kernel may co-schedule
    pdl_launch_dependents();

    extern __shared__ __align__(16) float sm[];
    const int b  = blockIdx.z;
    const int m0 = blockIdx.y * 128;
    const int n0 = blockIdx.x * 128;
    const float* A  = img + (size_t)b * C3 * L3;   // [k][m]
    const float* Bm = ref + (size_t)b * C3 * L3;   // [k][n]
    float* Cc = g_P + (size_t)b * L3 * L3;

    const int tid = threadIdx.x;
    const int lr  = tid >> 5;            // 0..7  (cp.async row)
    const int lc  = (tid & 31) * 4;      // cp.async col
    const int tx  = tid & 31;            // n group (lane)
    const int ty  = tid >> 5;            // m group (= warp id)

    const float* gA[4]; const float* gB[4];
    uint32_t sA[2][4], sB[2][4];
    #pragma unroll
    for (int i = 0; i < 4; i++) {
        gA[i] = &A [(size_t)(lr + 8 * i) * L3 + m0 + lc];
        gB[i] = &Bm[(size_t)(lr + 8 * i) * L3 + n0 + lc];
        #pragma unroll
        for (int u = 0; u < 2; u++) {
            sA[u][i] = (uint32_t)__cvta_generic_to_shared(
                &sm[u * 4096 + (lr + 8 * i) * 128 + lc]);
            sB[u][i] = (uint32_t)__cvta_generic_to_shared(
                &sm[8192 + u * 4096 + (lr + 8 * i) * 128 + lc]);
        }
    }
    const size_t kstep = (size_t)BK2 * L3;

    unsigned long long acc2[8][4];       // [m-pair][n]
    #pragma unroll
    for (int i = 0; i < 8; i++)
        #pragma unroll
        for (int j = 0; j < 4; j++) acc2[i][j] = 0ULL;

    #pragma unroll
    for (int i = 0; i < 4; i++) { cp_async16(sA[0][i], gA[i]); cp_async16(sB[0][i], gB[i]); }
    cp_commit();

    int buf = 0;
    for (int ks = 0; ks < C3 / BK2; ks++) {
        cp_wait0();
        __syncthreads();

        if (ks + 1 < C3 / BK2) {
            size_t off = (size_t)(ks + 1) * kstep;
            int nb = buf ^ 1;
            #pragma unroll
            for (int i = 0; i < 4; i++) {
                cp_async16(sA[nb][i], gA[i] + off);
                cp_async16(sB[nb][i], gB[i] + off);
            }
            cp_commit();
        }

        const float* Ab = &sm[buf * 4096];
        const float* Bb = &sm[8192 + buf * 4096];
        #pragma unroll 8
        for (int kk = 0; kk < BK2; kk++) {
            const float* Arow = &Ab[kk * 128 + ty * 16];
            float4 t0 = *(const float4*)(Arow);
            float4 t1 = *(const float4*)(Arow + 4);
            float4 t2 = *(const float4*)(Arow + 8);
            float4 t3 = *(const float4*)(Arow + 12);
            unsigned long long ap[8];
            ap[0] = ((unsigned long long*)&t0)[0]; ap[1] = ((unsigned long long*)&t0)[1];
            ap[2] = ((unsigned long long*)&t1)[0]; ap[3] = ((unsigned long long*)&t1)[1];
            ap[4] = ((unsigned long long*)&t2)[0]; ap[5] = ((unsigned long long*)&t2)[1];
            ap[6] = ((unsigned long long*)&t3)[0]; ap[7] = ((unsigned long long*)&t3)[1];
            float4 bv = *(const float4*)&Bb[kk * 128 + tx * 4];
            unsigned long long bb[4];
            bb[0] = bcast2(bv.x); bb[1] = bcast2(bv.y);
            bb[2] = bcast2(bv.z); bb[3] = bcast2(bv.w);
            #pragma unroll
            for (int p = 0; p < 8; p++) {
                fma2(acc2[p][0], ap[p], bb[0]);
                fma2(acc2[p][1], ap[p], bb[1]);
                fma2(acc2[p][2], ap[p], bb[2]);
                fma2(acc2[p][3], ap[p], bb[3]);
            }
        }
        buf ^= 1;
    }

    // epilogue: unpack pairs -> two float4 row stores per pair
    #pragma unroll
    for (int p = 0; p < 8; p++) {
        int m = m0 + ty * 16 + p * 2;
        float2 f0 = *(float2*)&acc2[p][0];
        float2 f1 = *(float2*)&acc2[p][1];
        float2 f2 = *(float2*)&acc2[p][2];
        float2 f3 = *(float2*)&acc2[p][3];
        float4 r0 = make_float4(f0.x, f1.x, f2.x, f3.x);   // row m
        float4 r1 = make_float4(f0.y, f1.y, f2.y, f3.y);   // row m+1
        *(float4*)&Cc[(size_t)m * L3 + n0 + tx * 4]       = r0;
        *(float4*)&Cc[(size_t)(m + 1) * L3 + n0 + tx * 4] = r1;
    }
}

// ---------------- 5a) x-pass: G[r][c] = A[c-1] + B[c] + C[c+1], 4 rows/block -
#define SRS 2312
__global__ void gpass1_kernel() {
    __shared__ __align__(16) float sR[6 * SRS];
    int r0 = blockIdx.x * 4, b = blockIdx.y;
    const float* Pb = g_P + (size_t)b * L3 * L3;
    float* Gb = g_G + (size_t)b * L3 * L3;
    int tid = threadIdx.x;

    #pragma unroll
    for (int i = 0; i < 6; i++) {
        int rr = min(max(r0 - 1 + i, 0), L3 - 1);   // clamped rows never used
        const float4* src = (const float4*)(Pb + (size_t)rr * L3);
        float4* dst = (float4*)&sR[i * SRS + 4];
        for (int g = tid; g < 576; g += 256) dst[g] = src[g];
    }
    __syncthreads();

    #pragma unroll
    for (int j = 0; j < 4; j++) {
        int r = r0 + j;
        int xq = r % H3;
        const float* Aj = &sR[j * SRS + 4];
        const float* Bj = &sR[(j + 1) * SRS + 4];
        const float* Cj = &sR[(j + 2) * SRS + 4];
        float* gr = Gb + (size_t)r * L3;
        bool hasA = (xq != 0), hasC = (xq != H3 - 1);

        if (hasA && hasC) {
            for (int g = tid; g < 576; g += 256) {
                int c = g * 4;
                int m = (g % 12) * 4;
                float4 bv = *(const float4*)&Bj[c];
                float a0 = (m != 0) ? Aj[c - 1] : 0.f;
                float c3 = (m != 44) ? Cj[c + 4] : 0.f;
                float4 o;
                o.x = a0        + bv.x + Cj[c + 1];
                o.y = Aj[c]     + bv.y + Cj[c + 2];
                o.z = Aj[c + 1] + bv.z + Cj[c + 3];
                o.w = Aj[c + 2] + bv.w + c3;
                *(float4*)&gr[c] = o;
            }
        } else if (!hasA) {
            for (int g = tid; g < 576; g += 256) {
                int c = g * 4;
                int m = (g % 12) * 4;
                float4 bv = *(const float4*)&Bj[c];
                float c3 = (m != 44) ? Cj[c + 4] : 0.f;
                float4 o;
                o.x = bv.x + Cj[c + 1];
                o.y = bv.y + Cj[c + 2];
                o.z = bv.z + Cj[c + 3];
                o.w = bv.w + c3;
                *(float4*)&gr[c] = o;
            }
        } else {
            for (int g = tid; g < 576; g += 256) {
                int c = g * 4;
                int m = (g % 12) * 4;
                float4 bv = *(const float4*)&Bj[c];
                float a0 = (m != 0) ? Aj[c - 1] : 0.f;
                float4 o;
                o.x = a0        + bv.x;
                o.y = Aj[c]     + bv.y;
                o.z = Aj[c + 1] + bv.z;
                o.w = Aj[c + 2] + bv.w;
                *(float4*)&gr[c] = o;
            }
        }
    }
    pdl_launch_dependents();
}

// ---------------- 5b) y-pass + max/argmax (straight-line 3 passes) -----------
__global__ void maxarg_kernel(float* __restrict__ outS) {
    int b = blockIdx.y, lq = blockIdx.x;
    int yq = lq / H3;
    const float4* Gb4 = (const float4*)(g_G + (size_t)b * L3 * L3);
    const float4* z4p = (const float4*)g_zero;

    const float4* rb[3];
    bool qv[3];
    #pragma unroll
    for (int t = 0; t < 3; t++) {
        int di = t - 1;
        qv[t] = ((unsigned)(yq + di) < H3);
        rb[t] = qv[t] ? (Gb4 + (size_t)(lq + 48 * di) * 576 + 12 * di) : z4p;
    }
    const float4* rnk4 = (const float4*)&g_nrm[1][b * L3];

    pdl_wait();     // g_G from gpass1 must be visible before loads

    const int tid = threadIdx.x;
    float best = -1e30f; int bi = 0;
    const float4 z4 = make_float4(0.f, 0.f, 0.f, 0.f);

    // pass 1: gi = tid (0..255). yk<=46 always (gi<564); yk>=1 iff gi>=12.
    {
        int gi = tid;
        bool k0 = qv[0] && (gi >= 12);
        float4 v0 = k0    ? rb[0][gi] : z4;
        float4 v1 = qv[1] ? rb[1][gi] : z4;
        float4 v2 = qv[2] ? rb[2][gi] : z4;
        float4 rk = rnk4[gi];
        float s0 = (v0.x + v1.x + v2.x) * rk.x;
        float s1 = (v0.y + v1.y + v2.y) * rk.y;
        float s2 = (v0.z + v1.z + v2.z) * rk.z;
        float s3 = (v0.w + v1.w + v2.w) * rk.w;
        int lk = gi * 4;
        if (s0 > best) { best = s0; bi = lk; }
        if (s1 > best) { best = s1; bi = lk + 1; }
        if (s2 > best) { best = s2; bi = lk + 2; }
        if (s3 > best) { best = s3; bi = lk + 3; }
    }
    // pass 2: gi = tid+256 (256..511). 12 <= gi < 564 -> no yk masks needed.
    {
        int gi = tid + 256;
        float4 v0 = qv[0] ? rb[0][gi] : z4;
        float4 v1 = qv[1] ? rb[1][gi] : z4;
        float4 v2 = qv[2] ? rb[2][gi] : z4;
        float4 rk = rnk4[gi];
        float s0 = (v0.x + v1.x + v2.x) * rk.x;
        float s1 = (v0.y + v1.y + v2.y) * rk.y;
        float s2 = (v0.z + v1.z + v2.z) * rk.z;
        float s3 = (v0.w + v1.w + v2.w) * rk.w;
        int lk = gi * 4;
        if (s0 > best) { best = s0; bi = lk; }
        if (s1 > best) { best = s1; bi = lk + 1; }
        if (s2 > best) { best = s2; bi = lk + 2; }
        if (s3 > best) { best = s3; bi = lk + 3; }
    }
    // pass 3: gi = tid+512 (512..575), only tid<64. yk>=1 always; yk<=46 iff gi<564.
    if (tid < 64) {
        int gi = tid + 512;
        bool k2 = qv[2] && (gi < 564);
        float4 v0 = qv[0] ? rb[0][gi] : z4;
        float4 v1 = qv[1] ? rb[1][gi] : z4;
        float4 v2 = k2    ? rb[2][gi] : z4;
        float4 rk = rnk4[gi];
        float s0 = (v0.x + v1.x + v2.x) * rk.x;
        float s1 = (v0.y + v1.y + v2.y) * rk.y;
        float s2 = (v0.z + v1.z + v2.z) * rk.z;
        float s3 = (v0.w + v1.w + v2.w) * rk.w;
        int lk = gi * 4;
        if (s0 > best) { best = s0; bi = lk; }
        if (s1 > best) { best = s1; bi = lk + 1; }
        if (s2 > best) { best = s2; bi = lk + 2; }
        if (s3 > best) { best = s3; bi = lk + 3; }
    }

    __shared__ float sv[256];
    __shared__ int   si[256];
    sv[tid] = best; si[tid] = bi;
    __syncthreads();
    for (int st = 128; st > 0; st >>= 1) {
        if (tid < st) {
            float o = sv[tid + st]; int oi = si[tid + st];
            if (o > sv[tid] || (o == sv[tid] && oi < si[tid])) {
                sv[tid] = o; si[tid] = oi;
            }
        }
        __syncthreads();
    }
    if (tid == 0) {
        g_idx[b * L3 + lq] = si[0];
        outS[b * L3 + lq]  = sv[0] / g_nrm[0][b * L3 + lq];
    }
    pdl_launch_dependents();
}

// ---------------- 6) merged gather + fold-normalize (all 3 levels) -----------
__global__ void __launch_bounds__(256) transfer_kernel(float* __restrict__ outT3,
                                                       float* __restrict__ outT2,
                                                       float* __restrict__ outT1) {
    __shared__ __align__(16) float acc[3456];    // xpc*(C+8) <= 3456 floats
    __shared__ __align__(16) int4 ent[3][14];    // {dxs, base4, ok, pad}
    __shared__ float sinv[12];
    int j = blockIdx.x;
    int tid = threadIdx.x;

    // segment decode
    const float* clT; float* out; int C, W, ls, xpc, b, y, zc;
    int seg;
    if (j < XB3) {
        seg = 0;
        clT = g_cl3T; out = outT3; C = C3; W = H3; ls = 0; xpc = 12;
        y = j % H3; b = (j / H3) & 3; zc = j / (H3 * 4);
    } else if (j < XB3 + XB2) {
        seg = 1;
        int q = j - XB3;
        clT = g_cl2T; out = outT2; C = C2; W = H2; ls = 1; xpc = 24;
        y = q % H2; b = (q / H2) & 3; zc = q / (H2 * 4);
    } else {
        seg = 2;
        int q = j - XB3 - XB2;
        clT = g_cl1T; out = outT1; C = C1; W = H1; ls = 2; xpc = 48;
        y = q % H1; b = (q / H1) & 3; zc = q / (H1 * 4);
    }
    int xlo = zc * xpc;
    int cpg  = C >> 2;
    int cg   = tid & (cpg - 1);
    int xsub = tid / cpg;
    int ppp  = 256 / cpg;
    int astr = C + 8;

    int tyq  = y >> ls;
    int txq0 = xlo >> ls;
    const int* idxb = g_idx + b * L3;

    pdl_wait();     // g_idx from maxarg must be visible

    if (tid < 42) {
        int a = tid / 14, xi = tid % 14;
        int xq = txq0 - 1 + xi;
        int yq = tyq - 1 + a;
        int dxs = 0, base4 = 0, ok = 0;
        if ((unsigned)xq < H3 && (unsigned)yq < H3) {
            int idx = idxb[yq * H3 + xq];
            int yk = idx / H3, xk = idx % H3;
            int ys = y + ((yk - yq) << ls);
            if ((unsigned)ys < (unsigned)W) {
                ok = 1;
                base4 = ys * W * (C >> 2);
            }
            dxs = (xk - xq) << ls;
        }
        ent[a][xi] = make_int4(dxs, base4, ok, 0);
    }
    if (tid < 12) {
        int txq = txq0 + tid;
        int nvx = 1 + (txq > 0) + (txq < H3 - 1);
        int nvy = 1 + (tyq > 0) + (tyq < H3 - 1);
        sinv[tid] = 1.0f / (float)(nvx * nvy);
    }
    __syncthreads();

    const float4* f4b = (const float4*)(clT + (size_t)b * W * W * C);

    for (int xo = 0; xo < xpc; xo += ppp) {
        int x = xlo + xo + xsub;
        int xib = (x >> ls) - txq0;
        float4 sum = make_float4(0.f, 0.f, 0.f, 0.f);
        #pragma unroll
        for (int a = 0; a < 3; a++) {
            #pragma unroll
            for (int dx = 0; dx < 3; dx++) {
                int4 e = ent[a][xib + dx];
                int xs = x + e.x;
                if (e.z && (unsigned)xs < (unsigned)W) {
                    float4 v = f4b[e.y + xs * cpg + cg];
                    sum.x += v.x; sum.y += v.y; sum.z += v.z; sum.w += v.w;
                }
            }
        }
        float ic = sinv[xib];
        *(float4*)&acc[(xo + xsub) * astr + cg * 4] =
            make_float4(sum.x * ic, sum.y * ic, sum.z * ic, sum.w * ic);
    }
    __syncthreads();

    // writeout with compile-time xpc per segment (div -> mul/shift)
    size_t ob = (size_t)b * C * W * W + (size_t)y * W + xlo;
    #define WRITEOUT(XPC_) do {                                            \
        for (int i = tid; i < C * (XPC_); i += 256) {                      \
            int c = i / (XPC_), x = i % (XPC_);                            \
            out[ob + (size_t)c * W * W + x] = acc[x * astr + c];           \
        }                                                                  \
    } while (0)
    if (seg == 0)      WRITEOUT(12);
    else if (seg == 1) WRITEOUT(24);
    else               WRITEOUT(48);
    #undef WRITEOUT
}

// ---------------- launch ------------------------------------------------------
static void launch_pdl(void* func, dim3 grid, dim3 block, void** args) {
    cudaLaunchConfig_t cfg = {};
    cfg.gridDim = grid;
    cfg.blockDim = block;
    cfg.dynamicSmemBytes = 0;
    cfg.stream = 0;
    cudaLaunchAttribute at;
    at.id = cudaLaunchAttributeProgrammaticStreamSerialization;
    at.val.programmaticStreamSerializationAllowed = 1;
    cfg.attrs = &at;
    cfg.numAttrs = 1;
    cudaLaunchKernelExC(&cfg, func, args);
}

extern "C" void kernel_launch(void* const* d_in, const int* in_sizes, int n_in,
                              void* d_out, int out_size) {
    const float* img = (const float*)d_in[0];   // dh_img_lv3 [4,256,48,48]
    const float* ref = (const float*)d_in[1];   // dh_ref_lv3 [4,256,48,48]
    const float* cl1 = (const float*)d_in[2];   // cl_ref_lv1 [4,64,192,192]
    const float* cl2 = (const float*)d_in[3];   // cl_ref_lv2 [4,128,96,96]
    const float* cl3 = (const float*)d_in[4];   // cl_ref_lv3 [4,256,48,48]

    float* outS  = (float*)d_out;               // [4,1,48,48]
    float* outT3 = outS  + BB * L3;             // [4,256,48,48]
    float* outT2 = outT3 + (size_t)BB * C3 * L3;    // [4,128,96,96]
    float* outT1 = outT2 + (size_t)BB * C2 * L2n;   // [4,64,192,192]

    cudaFuncSetAttribute(gemm_kernel,
                         cudaFuncAttributeMaxDynamicSharedMemorySize, GEMM_SMEM);

    // 0: GEMM (triggers PDL dependents at start)
    gemm_kernel<<<dim3(L3 / 128, L3 / 128, BB), 256, GEMM_SMEM>>>(img, ref);

    // 1: side work (transposes + norms), PDL so it fills gemm's gaps/tail
    {
        void* args[] = { (void*)&img, (void*)&ref, (void*)&cl1, (void*)&cl2, (void*)&cl3 };
        launch_pdl((void*)side_kernel, dim3(NSIDE), dim3(256), args);
    }

    // 2: x-pass (normal launch: full barrier on gemm + side)
    gpass1_kernel<<<dim3(L3 / 4, BB), 256>>>();

    // 3: y-pass + argmax (PDL after gpass1, profiled slot)
    {
        void* args[] = { (void*)&outS };
        launch_pdl((void*)maxarg_kernel, dim3(L3, BB), dim3(256), args);
    }

    // 4: all three transfers in one launch (PDL after maxarg)
    {
        void* args[] = { (void*)&outT3, (void*)&outT2, (void*)&outT1 };
        launch_pdl((void*)transfer_kernel, dim3(NXFER), dim3(256), args);
    }
}

// round 16
// speedup vs baseline: 1.1781x; 1.0446x over previous
#include <cuda_runtime.h>
#include <cstdint>

// Problem constants
#define BB   4
#define C3   256
#define H3   48
#define L3   (H3*H3)          // 2304
#define C2   128
#define H2   96
#define L2n  (H2*H2)          // 9216
#define C1   64
#define H1   192
#define L1n  (H1*H1)          // 36864
#define EPSN 1e-12f

#define BK2 32
#define GEMM_SMEM (2 * BK2 * 128 * 2 * 4)      // 65536 bytes

// side_kernel block counts
#define NSQB 72                                 // 9 tiles x 2 tensors x 4 batches
#define NT3  2304
#define NT2  4608
#define NT1  9216
#define NSIDE (NSQB + NT3 + NT2 + NT1)          // 16200

// merged transfer block counts
#define XB3 768                                 // 48*4*4
#define XB2 1536                                // 96*4*4
#define XB1 3072                                // 192*4*4
#define NXFER (XB3 + XB2 + XB1)                 // 5376

// ---------------- scratch (static device globals; no allocation) -------------
__device__ __align__(16) float g_P[(size_t)BB * L3 * L3];   // [b][lq][lk]  ~85MB
__device__ __align__(16) float g_G[(size_t)BB * L3 * L3];   // x-pass of shifted sum
__device__ __align__(16) float g_cl3T[(size_t)BB * L3 * C3];  // [b][pix][c]
__device__ __align__(16) float g_cl2T[(size_t)BB * L2n * C2];
__device__ __align__(16) float g_cl1T[(size_t)BB * L1n * C1];
__device__ __align__(16) float g_nrm[2][BB * L3];     // 0: nq(img) norm, 1: 1/nk(ref)
__device__ int   g_idx[BB * L3];                      // argmax index per query
__device__ __align__(16) float g_zero[16];            // stays zero (never written)

// ---------------- helpers -----------------------------------------------------
__device__ __forceinline__ void cp_async16(uint32_t smem, const void* gmem) {
    asm volatile("cp.async.cg.shared.global [%0], [%1], 16;\n" :: "r"(smem), "l"(gmem));
}
__device__ __forceinline__ void cp_commit() {
    asm volatile("cp.async.commit_group;\n" ::: "memory");
}
__device__ __forceinline__ void cp_wait0() {
    asm volatile("cp.async.wait_group 0;\n" ::: "memory");
}
// packed fp32x2 FMA: d = a*b + d  (componentwise, exact fp32 semantics)
__device__ __forceinline__ void fma2(unsigned long long& d, unsigned long long a,
                                     unsigned long long b) {
    asm("fma.rn.f32x2 %0, %1, %2, %0;" : "+l"(d) : "l"(a), "l"(b));
}
__device__ __forceinline__ unsigned long long bcast2(float x) {
    unsigned long long r;
    asm("mov.b64 %0, {%1, %1};" : "=l"(r) : "f"(x));
    return r;
}
__device__ __forceinline__ void pdl_launch_dependents() {
    asm volatile("griddepcontrol.launch_dependents;" ::: "memory");
}
__device__ __forceinline__ void pdl_wait() {
    asm volatile("griddepcontrol.wait;" ::: "memory");
}

// ---------------- side kernel: 3 transposes + fused sqsum/boxnorm ------------
// Launched FIRST; signals dependents (GEMM) immediately so GEMM back-fills SMs
// as side blocks drain.
__global__ void __launch_bounds__(256) side_kernel(const float* __restrict__ img,
                                                   const float* __restrict__ ref,
                                                   const float* __restrict__ cl1,
                                                   const float* __restrict__ cl2,
                                                   const float* __restrict__ cl3) {
    pdl_launch_dependents();

    __shared__ float sbuf[1056];                 // transpose 32x33; sqsumbox uses 324
    int j = blockIdx.x;
    int tid = threadIdx.x;

    if (j < NSQB) {
        // ---- fused per-pixel sqnorm + 3x3 box-sum -> patch norm ----
        int tile = j % 9, which = (j / 9) & 1, b = j / 18;
        const float* src = ((which == 0) ? img : ref) + (size_t)b * C3 * L3;
        int ty0 = (tile / 3) * 16, tx0 = (tile % 3) * 16;
        for (int p = tid; p < 324; p += 256) {
            int py = ty0 + p / 18 - 1, px = tx0 + p % 18 - 1;
            float s = 0.f;
            if ((unsigned)py < H3 && (unsigned)px < H3) {
                const float* sp = src + py * H3 + px;
                #pragma unroll 4
                for (int c = 0; c < C3; c++) {
                    float v = sp[(size_t)c * L3];
                    s += v * v;
                }
            }
            sbuf[p] = s;
        }
        __syncthreads();
        {
            int py = tid / 16, px = tid % 16;       // all 256 threads
            float acc = 0.f;
            #pragma unroll
            for (int dy = 0; dy < 3; dy++)
                #pragma unroll
                for (int dx = 0; dx < 3; dx++)
                    acc += sbuf[(py + dy) * 18 + px + dx];
            float n = fmaxf(sqrtf(acc), EPSN);
            g_nrm[which][b * L3 + (ty0 + py) * H3 + tx0 + px] = which ? (1.0f / n) : n;
        }
        return;
    }

    // ---- transpose cl -> channel-last ----
    int q = j - NSQB;
    const float* src; float* dst; int C, L;
    if (q < NT3)            { src = cl3; dst = g_cl3T; C = C3; L = L3; }
    else if (q < NT3 + NT2) { q -= NT3;  src = cl2; dst = g_cl2T; C = C2; L = L2n; }
    else                    { q -= NT3 + NT2; src = cl1; dst = g_cl1T; C = C1; L = L1n; }
    int nl = L / 32, nc = C / 32;
    int l0 = (q % nl) * 32, c0 = ((q / nl) % nc) * 32, b = q / (nl * nc);
    const float* s = src + (size_t)b * C * L;
    float* d = dst + (size_t)b * L * C;
    int txx = tid % 32, tyy = tid / 32;
    #pragma unroll
    for (int i = tyy; i < 32; i += 8)
        sbuf[i * 33 + txx] = s[(size_t)(c0 + i) * L + l0 + txx];
    __syncthreads();
    #pragma unroll
    for (int i = tyy; i < 32; i += 8)
        d[(size_t)(l0 + i) * C + c0 + txx] = sbuf[txx * 33 + i];
}

// ---------------- 4) SGEMM via packed FFMA2, 16m x 4n packed-m microtile -----
// Launched as PSS dependent of side_kernel; no data dependency on side.
__global__ void __launch_bounds__(256, 2) gemm_kernel(const float* __restrict__ img,
                                                      const float* __restrict__ ref) {
    extern __shared__ __align__(16) float sm[];
    const int b  = blockIdx.z;
    const int m0 = blockIdx.y * 128;
    const int n0 = blockIdx.x * 128;
    const float* A  = img + (size_t)b * C3 * L3;   // [k][m]
    const float* Bm = ref + (size_t)b * C3 * L3;   // [k][n]
    float* Cc = g_P + (size_t)b * L3 * L3;

    const int tid = threadIdx.x;
    const int lr  = tid >> 5;            // 0..7  (cp.async row)
    const int lc  = (tid & 31) * 4;      // cp.async col
    const int tx  = tid & 31;            // n group (lane)
    const int ty  = tid >> 5;            // m group (= warp id)

    const float* gA[4]; const float* gB[4];
    uint32_t sA[2][4], sB[2][4];
    #pragma unroll
    for (int i = 0; i < 4; i++) {
        gA[i] = &A [(size_t)(lr + 8 * i) * L3 + m0 + lc];
        gB[i] = &Bm[(size_t)(lr + 8 * i) * L3 + n0 + lc];
        #pragma unroll
        for (int u = 0; u < 2; u++) {
            sA[u][i] = (uint32_t)__cvta_generic_to_shared(
                &sm[u * 4096 + (lr + 8 * i) * 128 + lc]);
            sB[u][i] = (uint32_t)__cvta_generic_to_shared(
                &sm[8192 + u * 4096 + (lr + 8 * i) * 128 + lc]);
        }
    }
    const size_t kstep = (size_t)BK2 * L3;

    unsigned long long acc2[8][4];       // [m-pair][n]
    #pragma unroll
    for (int i = 0; i < 8; i++)
        #pragma unroll
        for (int j = 0; j < 4; j++) acc2[i][j] = 0ULL;

    #pragma unroll
    for (int i = 0; i < 4; i++) { cp_async16(sA[0][i], gA[i]); cp_async16(sB[0][i], gB[i]); }
    cp_commit();

    int buf = 0;
    for (int ks = 0; ks < C3 / BK2; ks++) {
        cp_wait0();
        __syncthreads();

        if (ks + 1 < C3 / BK2) {
            size_t off = (size_t)(ks + 1) * kstep;
            int nb = buf ^ 1;
            #pragma unroll
            for (int i = 0; i < 4; i++) {
                cp_async16(sA[nb][i], gA[i] + off);
                cp_async16(sB[nb][i], gB[i] + off);
            }
            cp_commit();
        }

        const float* Ab = &sm[buf * 4096];
        const float* Bb = &sm[8192 + buf * 4096];
        #pragma unroll 8
        for (int kk = 0; kk < BK2; kk++) {
            const float* Arow = &Ab[kk * 128 + ty * 16];
            float4 t0 = *(const float4*)(Arow);
            float4 t1 = *(const float4*)(Arow + 4);
            float4 t2 = *(const float4*)(Arow + 8);
            float4 t3 = *(const float4*)(Arow + 12);
            unsigned long long ap[8];
            ap[0] = ((unsigned long long*)&t0)[0]; ap[1] = ((unsigned long long*)&t0)[1];
            ap[2] = ((unsigned long long*)&t1)[0]; ap[3] = ((unsigned long long*)&t1)[1];
            ap[4] = ((unsigned long long*)&t2)[0]; ap[5] = ((unsigned long long*)&t2)[1];
            ap[6] = ((unsigned long long*)&t3)[0]; ap[7] = ((unsigned long long*)&t3)[1];
            float4 bv = *(const float4*)&Bb[kk * 128 + tx * 4];
            unsigned long long bb[4];
            bb[0] = bcast2(bv.x); bb[1] = bcast2(bv.y);
            bb[2] = bcast2(bv.z); bb[3] = bcast2(bv.w);
            #pragma unroll
            for (int p = 0; p < 8; p++) {
                fma2(acc2[p][0], ap[p], bb[0]);
                fma2(acc2[p][1], ap[p], bb[1]);
                fma2(acc2[p][2], ap[p], bb[2]);
                fma2(acc2[p][3], ap[p], bb[3]);
            }
        }
        buf ^= 1;
    }

    // epilogue: unpack pairs -> two float4 row stores per pair
    #pragma unroll
    for (int p = 0; p < 8; p++) {
        int m = m0 + ty * 16 + p * 2;
        float2 f0 = *(float2*)&acc2[p][0];
        float2 f1 = *(float2*)&acc2[p][1];
        float2 f2 = *(float2*)&acc2[p][2];
        float2 f3 = *(float2*)&acc2[p][3];
        float4 r0 = make_float4(f0.x, f1.x, f2.x, f3.x);   // row m
        float4 r1 = make_float4(f0.y, f1.y, f2.y, f3.y);   // row m+1
        *(float4*)&Cc[(size_t)m * L3 + n0 + tx * 4]       = r0;
        *(float4*)&Cc[(size_t)(m + 1) * L3 + n0 + tx * 4] = r1;
    }
}

// ---------------- 5a) x-pass: G[r][c] = A[c-1] + B[c] + C[c+1], 4 rows/block -
#define SRS 2312
__global__ void gpass1_kernel() {
    __shared__ __align__(16) float sR[6 * SRS];
    int r0 = blockIdx.x * 4, b = blockIdx.y;
    const float* Pb = g_P + (size_t)b * L3 * L3;
    float* Gb = g_G + (size_t)b * L3 * L3;
    int tid = threadIdx.x;

    #pragma unroll
    for (int i = 0; i < 6; i++) {
        int rr = min(max(r0 - 1 + i, 0), L3 - 1);   // clamped rows never used
        const float4* src = (const float4*)(Pb + (size_t)rr * L3);
        float4* dst = (float4*)&sR[i * SRS + 4];
        for (int g = tid; g < 576; g += 256) dst[g] = src[g];
    }
    __syncthreads();

    #pragma unroll
    for (int j = 0; j < 4; j++) {
        int r = r0 + j;
        int xq = r % H3;
        const float* Aj = &sR[j * SRS + 4];
        const float* Bj = &sR[(j + 1) * SRS + 4];
        const float* Cj = &sR[(j + 2) * SRS + 4];
        float* gr = Gb + (size_t)r * L3;
        bool hasA = (xq != 0), hasC = (xq != H3 - 1);

        if (hasA && hasC) {
            for (int g = tid; g < 576; g += 256) {
                int c = g * 4;
                int m = (g % 12) * 4;
                float4 bv = *(const float4*)&Bj[c];
                float a0 = (m != 0) ? Aj[c - 1] : 0.f;
                float c3 = (m != 44) ? Cj[c + 4] : 0.f;
                float4 o;
                o.x = a0        + bv.x + Cj[c + 1];
                o.y = Aj[c]     + bv.y + Cj[c + 2];
                o.z = Aj[c + 1] + bv.z + Cj[c + 3];
                o.w = Aj[c + 2] + bv.w + c3;
                *(float4*)&gr[c] = o;
            }
        } else if (!hasA) {
            for (int g = tid; g < 576; g += 256) {
                int c = g * 4;
                int m = (g % 12) * 4;
                float4 bv = *(const float4*)&Bj[c];
                float c3 = (m != 44) ? Cj[c + 4] : 0.f;
                float4 o;
                o.x = bv.x + Cj[c + 1];
                o.y = bv.y + Cj[c + 2];
                o.z = bv.z + Cj[c + 3];
                o.w = bv.w + c3;
                *(float4*)&gr[c] = o;
            }
        } else {
            for (int g = tid; g < 576; g += 256) {
                int c = g * 4;
                int m = (g % 12) * 4;
                float4 bv = *(const float4*)&Bj[c];
                float a0 = (m != 0) ? Aj[c - 1] : 0.f;
                float4 o;
                o.x = a0        + bv.x;
                o.y = Aj[c]     + bv.y;
                o.z = Aj[c + 1] + bv.z;
                o.w = Aj[c + 2] + bv.w;
                *(float4*)&gr[c] = o;
            }
        }
    }
    pdl_launch_dependents();
}

// ---------------- 5b) y-pass + max/argmax (straight-line 3 passes) -----------
__global__ void maxarg_kernel(float* __restrict__ outS) {
    int b = blockIdx.y, lq = blockIdx.x;
    int yq = lq / H3;
    const float4* Gb4 = (const float4*)(g_G + (size_t)b * L3 * L3);
    const float4* z4p = (const float4*)g_zero;

    const float4* rb[3];
    bool qv[3];
    #pragma unroll
    for (int t = 0; t < 3; t++) {
        int di = t - 1;
        qv[t] = ((unsigned)(yq + di) < H3);
        rb[t] = qv[t] ? (Gb4 + (size_t)(lq + 48 * di) * 576 + 12 * di) : z4p;
    }
    const float4* rnk4 = (const float4*)&g_nrm[1][b * L3];

    pdl_wait();     // g_G from gpass1 must be visible before loads

    const int tid = threadIdx.x;
    float best = -1e30f; int bi = 0;
    const float4 z4 = make_float4(0.f, 0.f, 0.f, 0.f);

    // pass 1: gi = tid (0..255). yk<=46 always (gi<564); yk>=1 iff gi>=12.
    {
        int gi = tid;
        bool k0 = qv[0] && (gi >= 12);
        float4 v0 = k0    ? rb[0][gi] : z4;
        float4 v1 = qv[1] ? rb[1][gi] : z4;
        float4 v2 = qv[2] ? rb[2][gi] : z4;
        float4 rk = rnk4[gi];
        float s0 = (v0.x + v1.x + v2.x) * rk.x;
        float s1 = (v0.y + v1.y + v2.y) * rk.y;
        float s2 = (v0.z + v1.z + v2.z) * rk.z;
        float s3 = (v0.w + v1.w + v2.w) * rk.w;
        int lk = gi * 4;
        if (s0 > best) { best = s0; bi = lk; }
        if (s1 > best) { best = s1; bi = lk + 1; }
        if (s2 > best) { best = s2; bi = lk + 2; }
        if (s3 > best) { best = s3; bi = lk + 3; }
    }
    // pass 2: gi = tid+256 (256..511). 12 <= gi < 564 -> no yk masks needed.
    {
        int gi = tid + 256;
        float4 v0 = qv[0] ? rb[0][gi] : z4;
        float4 v1 = qv[1] ? rb[1][gi] : z4;
        float4 v2 = qv[2] ? rb[2][gi] : z4;
        float4 rk = rnk4[gi];
        float s0 = (v0.x + v1.x + v2.x) * rk.x;
        float s1 = (v0.y + v1.y + v2.y) * rk.y;
        float s2 = (v0.z + v1.z + v2.z) * rk.z;
        float s3 = (v0.w + v1.w + v2.w) * rk.w;
        int lk = gi * 4;
        if (s0 > best) { best = s0; bi = lk; }
        if (s1 > best) { best = s1; bi = lk + 1; }
        if (s2 > best) { best = s2; bi = lk + 2; }
        if (s3 > best) { best = s3; bi = lk + 3; }
    }
    // pass 3: gi = tid+512 (512..575), only tid<64. yk>=1 always; yk<=46 iff gi<564.
    if (tid < 64) {
        int gi = tid + 512;
        bool k2 = qv[2] && (gi < 564);
        float4 v0 = qv[0] ? rb[0][gi] : z4;
        float4 v1 = qv[1] ? rb[1][gi] : z4;
        float4 v2 = k2    ? rb[2][gi] : z4;
        float4 rk = rnk4[gi];
        float s0 = (v0.x + v1.x + v2.x) * rk.x;
        float s1 = (v0.y + v1.y + v2.y) * rk.y;
        float s2 = (v0.z + v1.z + v2.z) * rk.z;
        float s3 = (v0.w + v1.w + v2.w) * rk.w;
        int lk = gi * 4;
        if (s0 > best) { best = s0; bi = lk; }
        if (s1 > best) { best = s1; bi = lk + 1; }
        if (s2 > best) { best = s2; bi = lk + 2; }
        if (s3 > best) { best = s3; bi = lk + 3; }
    }

    __shared__ float sv[256];
    __shared__ int   si[256];
    sv[tid] = best; si[tid] = bi;
    __syncthreads();
    for (int st = 128; st > 0; st >>= 1) {
        if (tid < st) {
            float o = sv[tid + st]; int oi = si[tid + st];
            if (o > sv[tid] || (o == sv[tid] && oi < si[tid])) {
                sv[tid] = o; si[tid] = oi;
            }
        }
        __syncthreads();
    }
    if (tid == 0) {
        g_idx[b * L3 + lq] = si[0];
        outS[b * L3 + lq]  = sv[0] / g_nrm[0][b * L3 + lq];
    }
    pdl_launch_dependents();
}

// ---------------- 6) merged gather + fold-normalize (all 3 levels) -----------
__global__ void __launch_bounds__(256) transfer_kernel(float* __restrict__ outT3,
                                                       float* __restrict__ outT2,
                                                       float* __restrict__ outT1) {
    __shared__ __align__(16) float acc[3456];    // xpc*(C+8) <= 3456 floats
    __shared__ __align__(16) int4 ent[3][14];    // {dxs, base4, ok, pad}
    __shared__ float sinv[12];
    int j = blockIdx.x;
    int tid = threadIdx.x;

    // segment decode
    const float* clT; float* out; int C, W, ls, xpc, b, y, zc;
    int seg;
    if (j < XB3) {
        seg = 0;
        clT = g_cl3T; out = outT3; C = C3; W = H3; ls = 0; xpc = 12;
        y = j % H3; b = (j / H3) & 3; zc = j / (H3 * 4);
    } else if (j < XB3 + XB2) {
        seg = 1;
        int q = j - XB3;
        clT = g_cl2T; out = outT2; C = C2; W = H2; ls = 1; xpc = 24;
        y = q % H2; b = (q / H2) & 3; zc = q / (H2 * 4);
    } else {
        seg = 2;
        int q = j - XB3 - XB2;
        clT = g_cl1T; out = outT1; C = C1; W = H1; ls = 2; xpc = 48;
        y = q % H1; b = (q / H1) & 3; zc = q / (H1 * 4);
    }
    int xlo = zc * xpc;
    int cpg  = C >> 2;
    int cg   = tid & (cpg - 1);
    int xsub = tid / cpg;
    int ppp  = 256 / cpg;
    int astr = C + 8;

    int tyq  = y >> ls;
    int txq0 = xlo >> ls;
    const int* idxb = g_idx + b * L3;

    pdl_wait();     // g_idx from maxarg must be visible

    if (tid < 42) {
        int a = tid / 14, xi = tid % 14;
        int xq = txq0 - 1 + xi;
        int yq = tyq - 1 + a;
        int dxs = 0, base4 = 0, ok = 0;
        if ((unsigned)xq < H3 && (unsigned)yq < H3) {
            int idx = idxb[yq * H3 + xq];
            int yk = idx / H3, xk = idx % H3;
            int ys = y + ((yk - yq) << ls);
            if ((unsigned)ys < (unsigned)W) {
                ok = 1;
                base4 = ys * W * (C >> 2);
            }
            dxs = (xk - xq) << ls;
        }
        ent[a][xi] = make_int4(dxs, base4, ok, 0);
    }
    if (tid < 12) {
        int txq = txq0 + tid;
        int nvx = 1 + (txq > 0) + (txq < H3 - 1);
        int nvy = 1 + (tyq > 0) + (tyq < H3 - 1);
        sinv[tid] = 1.0f / (float)(nvx * nvy);
    }
    __syncthreads();

    const float4* f4b = (const float4*)(clT + (size_t)b * W * W * C);

    for (int xo = 0; xo < xpc; xo += ppp) {
        int x = xlo + xo + xsub;
        int xib = (x >> ls) - txq0;
        float4 sum = make_float4(0.f, 0.f, 0.f, 0.f);
        #pragma unroll
        for (int a = 0; a < 3; a++) {
            #pragma unroll
            for (int dx = 0; dx < 3; dx++) {
                int4 e = ent[a][xib + dx];
                int xs = x + e.x;
                if (e.z && (unsigned)xs < (unsigned)W) {
                    float4 v = f4b[e.y + xs * cpg + cg];
                    sum.x += v.x; sum.y += v.y; sum.z += v.z; sum.w += v.w;
                }
            }
        }
        float ic = sinv[xib];
        *(float4*)&acc[(xo + xsub) * astr + cg * 4] =
            make_float4(sum.x * ic, sum.y * ic, sum.z * ic, sum.w * ic);
    }
    __syncthreads();

    // writeout with compile-time xpc per segment (div -> mul/shift)
    size_t ob = (size_t)b * C * W * W + (size_t)y * W + xlo;
    #define WRITEOUT(XPC_) do {                                            \
        for (int i = tid; i < C * (XPC_); i += 256) {                      \
            int c = i / (XPC_), x = i % (XPC_);                            \
            out[ob + (size_t)c * W * W + x] = acc[x * astr + c];           \
        }                                                                  \
    } while (0)
    if (seg == 0)      WRITEOUT(12);
    else if (seg == 1) WRITEOUT(24);
    else               WRITEOUT(48);
    #undef WRITEOUT
}

// ---------------- launch ------------------------------------------------------
static cudaError_t launch_pdl(void* func, dim3 grid, dim3 block, void** args,
                              size_t smem) {
    cudaLaunchConfig_t cfg = {};
    cfg.gridDim = grid;
    cfg.blockDim = block;
    cfg.dynamicSmemBytes = smem;
    cfg.stream = 0;
    cudaLaunchAttribute at;
    at.id = cudaLaunchAttributeProgrammaticStreamSerialization;
    at.val.programmaticStreamSerializationAllowed = 1;
    cfg.attrs = &at;
    cfg.numAttrs = 1;
    return cudaLaunchKernelExC(&cfg, func, args);
}

extern "C" void kernel_launch(void* const* d_in, const int* in_sizes, int n_in,
                              void* d_out, int out_size) {
    const float* img = (const float*)d_in[0];   // dh_img_lv3 [4,256,48,48]
    const float* ref = (const float*)d_in[1];   // dh_ref_lv3 [4,256,48,48]
    const float* cl1 = (const float*)d_in[2];   // cl_ref_lv1 [4,64,192,192]
    const float* cl2 = (const float*)d_in[3];   // cl_ref_lv2 [4,128,96,96]
    const float* cl3 = (const float*)d_in[4];   // cl_ref_lv3 [4,256,48,48]

    float* outS  = (float*)d_out;               // [4,1,48,48]
    float* outT3 = outS  + BB * L3;             // [4,256,48,48]
    float* outT2 = outT3 + (size_t)BB * C3 * L3;    // [4,128,96,96]
    float* outT1 = outT2 + (size_t)BB * C2 * L2n;   // [4,64,192,192]

    cudaFuncSetAttribute(gemm_kernel,
                         cudaFuncAttributeMaxDynamicSharedMemorySize, GEMM_SMEM);

    // 0: side work FIRST (normal launch); signals dependents at start
    side_kernel<<<NSIDE, 256>>>(img, ref, cl1, cl2, cl3);

    // 1: GEMM as PSS dependent — back-fills SMs as side blocks drain
    {
        void* args[] = { (void*)&img, (void*)&ref };
        if (launch_pdl((void*)gemm_kernel, dim3(L3 / 128, L3 / 128, BB),
                       dim3(256), args, GEMM_SMEM) != cudaSuccess) {
            gemm_kernel<<<dim3(L3 / 128, L3 / 128, BB), 256, GEMM_SMEM>>>(img, ref);
        }
    }

    // 2: x-pass (NORMAL launch: hard barrier on side + gemm)
    gpass1_kernel<<<dim3(L3 / 4, BB), 256>>>();

    // 3: y-pass + argmax (PSS after gpass1; pdl_wait before g_G reads)
    {
        void* args[] = { (void*)&outS };
        if (launch_pdl((void*)maxarg_kernel, dim3(L3, BB), dim3(256), args, 0)
            != cudaSuccess) {
            maxarg_kernel<<<dim3(L3, BB), 256>>>(outS);
        }
    }

    // 4: all three transfers in one launch (PSS after maxarg; pdl_wait before g_idx)
    {
        void* args[] = { (void*)&outT3, (void*)&outT2, (void*)&outT1 };
        if (launch_pdl((void*)transfer_kernel, dim3(NXFER), dim3(256), args, 0)
            != cudaSuccess) {
            transfer_kernel<<<NXFER, 256>>>(outT3, outT2, outT1);
        }
    }
}

// round 17
// speedup vs baseline: 1.1839x; 1.0049x over previous
#include <cuda_runtime.h>
#include <cstdint>

// Problem constants
#define BB   4
#define C3   256
#define H3   48
#define L3   (H3*H3)          // 2304
#define C2   128
#define H2   96
#define L2n  (H2*H2)          // 9216
#define C1   64
#define H1   192
#define L1n  (H1*H1)          // 36864
#define EPSN 1e-12f

#define BK2 32
#define GEMM_SMEM (2 * BK2 * 128 * 2 * 4)      // 65536 bytes

// side_kernel block counts
#define NSQB 72                                 // 9 tiles x 2 tensors x 4 batches
#define NT3  2304
#define NT2  4608
#define NT1  9216
#define NSIDE (NSQB + NT3 + NT2 + NT1)          // 16200

// merged transfer block counts
#define XB3 768                                 // 48*4*4
#define XB2 1536                                // 96*4*4
#define XB1 3072                                // 192*4*4
#define NXFER (XB3 + XB2 + XB1)                 // 5376

// ---------------- scratch (static device globals; no allocation) -------------
__device__ __align__(16) float g_P[(size_t)BB * L3 * L3];   // [b][lq][lk]  ~85MB
__device__ __align__(16) float g_G[(size_t)BB * L3 * L3];   // x-pass of shifted sum
__device__ __align__(16) float g_cl3T[(size_t)BB * L3 * C3];  // [b][pix][c]
__device__ __align__(16) float g_cl2T[(size_t)BB * L2n * C2];
__device__ __align__(16) float g_cl1T[(size_t)BB * L1n * C1];
__device__ __align__(16) float g_nrm[2][BB * L3];     // 0: nq(img) norm, 1: 1/nk(ref)
__device__ int   g_idx[BB * L3];                      // argmax index per query
__device__ __align__(16) float g_zero[16];            // stays zero (never written)

// ---------------- helpers -----------------------------------------------------
__device__ __forceinline__ void cp_async16(uint32_t smem, const void* gmem) {
    asm volatile("cp.async.cg.shared.global [%0], [%1], 16;\n" :: "r"(smem), "l"(gmem));
}
__device__ __forceinline__ void cp_commit() {
    asm volatile("cp.async.commit_group;\n" ::: "memory");
}
__device__ __forceinline__ void cp_wait0() {
    asm volatile("cp.async.wait_group 0;\n" ::: "memory");
}
// packed fp32x2 FMA: d = a*b + d  (componentwise, exact fp32 semantics)
__device__ __forceinline__ void fma2(unsigned long long& d, unsigned long long a,
                                     unsigned long long b) {
    asm("fma.rn.f32x2 %0, %1, %2, %0;" : "+l"(d) : "l"(a), "l"(b));
}
__device__ __forceinline__ unsigned long long bcast2(float x) {
    unsigned long long r;
    asm("mov.b64 %0, {%1, %1};" : "=l"(r) : "f"(x));
    return r;
}
__device__ __forceinline__ void pdl_launch_dependents() {
    asm volatile("griddepcontrol.launch_dependents;" ::: "memory");
}
__device__ __forceinline__ void pdl_wait() {
    asm volatile("griddepcontrol.wait;" ::: "memory");
}

// ---------------- side kernel: 3 transposes + fused sqsum/boxnorm ------------
// Launched FIRST; signals dependents (GEMM) immediately so GEMM back-fills SMs
// as side blocks drain.
__global__ void __launch_bounds__(256) side_kernel(const float* __restrict__ img,
                                                   const float* __restrict__ ref,
                                                   const float* __restrict__ cl1,
                                                   const float* __restrict__ cl2,
                                                   const float* __restrict__ cl3) {
    pdl_launch_dependents();

    __shared__ float sbuf[1056];                 // transpose 32x33; sqsumbox uses 324
    int j = blockIdx.x;
    int tid = threadIdx.x;

    if (j < NSQB) {
        // ---- fused per-pixel sqnorm + 3x3 box-sum -> patch norm ----
        int tile = j % 9, which = (j / 9) & 1, b = j / 18;
        const float* src = ((which == 0) ? img : ref) + (size_t)b * C3 * L3;
        int ty0 = (tile / 3) * 16, tx0 = (tile % 3) * 16;
        for (int p = tid; p < 324; p += 256) {
            int py = ty0 + p / 18 - 1, px = tx0 + p % 18 - 1;
            float s = 0.f;
            if ((unsigned)py < H3 && (unsigned)px < H3) {
                const float* sp = src + py * H3 + px;
                #pragma unroll 4
                for (int c = 0; c < C3; c++) {
                    float v = sp[(size_t)c * L3];
                    s += v * v;
                }
            }
            sbuf[p] = s;
        }
        __syncthreads();
        {
            int py = tid / 16, px = tid % 16;       // all 256 threads
            float acc = 0.f;
            #pragma unroll
            for (int dy = 0; dy < 3; dy++)
                #pragma unroll
                for (int dx = 0; dx < 3; dx++)
                    acc += sbuf[(py + dy) * 18 + px + dx];
            float n = fmaxf(sqrtf(acc), EPSN);
            g_nrm[which][b * L3 + (ty0 + py) * H3 + tx0 + px] = which ? (1.0f / n) : n;
        }
        return;
    }

    // ---- transpose cl -> channel-last ----
    int q = j - NSQB;
    const float* src; float* dst; int C, L;
    if (q < NT3)            { src = cl3; dst = g_cl3T; C = C3; L = L3; }
    else if (q < NT3 + NT2) { q -= NT3;  src = cl2; dst = g_cl2T; C = C2; L = L2n; }
    else                    { q -= NT3 + NT2; src = cl1; dst = g_cl1T; C = C1; L = L1n; }
    int nl = L / 32, nc = C / 32;
    int l0 = (q % nl) * 32, c0 = ((q / nl) % nc) * 32, b = q / (nl * nc);
    const float* s = src + (size_t)b * C * L;
    float* d = dst + (size_t)b * L * C;
    int txx = tid % 32, tyy = tid / 32;
    #pragma unroll
    for (int i = tyy; i < 32; i += 8)
        sbuf[i * 33 + txx] = s[(size_t)(c0 + i) * L + l0 + txx];
    __syncthreads();
    #pragma unroll
    for (int i = tyy; i < 32; i += 8)
        d[(size_t)(l0 + i) * C + c0 + txx] = sbuf[txx * 33 + i];
}

// ---------------- 4) SGEMM via packed FFMA2, 16m x 4n packed-m microtile -----
// Launched as PSS dependent of side_kernel; no data dependency on side.
__global__ void __launch_bounds__(256, 2) gemm_kernel(const float* __restrict__ img,
                                                      const float* __restrict__ ref) {
    extern __shared__ __align__(16) float sm[];
    const int b  = blockIdx.z;
    const int m0 = blockIdx.y * 128;
    const int n0 = blockIdx.x * 128;
    const float* A  = img + (size_t)b * C3 * L3;   // [k][m]
    const float* Bm = ref + (size_t)b * C3 * L3;   // [k][n]
    float* Cc = g_P + (size_t)b * L3 * L3;

    const int tid = threadIdx.x;
    const int lr  = tid >> 5;            // 0..7  (cp.async row)
    const int lc  = (tid & 31) * 4;      // cp.async col
    const int tx  = tid & 31;            // n group (lane)
    const int ty  = tid >> 5;            // m group (= warp id)

    const float* gA[4]; const float* gB[4];
    uint32_t sA[2][4], sB[2][4];
    #pragma unroll
    for (int i = 0; i < 4; i++) {
        gA[i] = &A [(size_t)(lr + 8 * i) * L3 + m0 + lc];
        gB[i] = &Bm[(size_t)(lr + 8 * i) * L3 + n0 + lc];
        #pragma unroll
        for (int u = 0; u < 2; u++) {
            sA[u][i] = (uint32_t)__cvta_generic_to_shared(
                &sm[u * 4096 + (lr + 8 * i) * 128 + lc]);
            sB[u][i] = (uint32_t)__cvta_generic_to_shared(
                &sm[8192 + u * 4096 + (lr + 8 * i) * 128 + lc]);
        }
    }
    const size_t kstep = (size_t)BK2 * L3;

    unsigned long long acc2[8][4];       // [m-pair][n]
    #pragma unroll
    for (int i = 0; i < 8; i++)
        #pragma unroll
        for (int j = 0; j < 4; j++) acc2[i][j] = 0ULL;

    #pragma unroll
    for (int i = 0; i < 4; i++) { cp_async16(sA[0][i], gA[i]); cp_async16(sB[0][i], gB[i]); }
    cp_commit();

    int buf = 0;
    for (int ks = 0; ks < C3 / BK2; ks++) {
        cp_wait0();
        __syncthreads();

        if (ks + 1 < C3 / BK2) {
            size_t off = (size_t)(ks + 1) * kstep;
            int nb = buf ^ 1;
            #pragma unroll
            for (int i = 0; i < 4; i++) {
                cp_async16(sA[nb][i], gA[i] + off);
                cp_async16(sB[nb][i], gB[i] + off);
            }
            cp_commit();
        }

        const float* Ab = &sm[buf * 4096];
        const float* Bb = &sm[8192 + buf * 4096];
        #pragma unroll 8
        for (int kk = 0; kk < BK2; kk++) {
            const float* Arow = &Ab[kk * 128 + ty * 16];
            float4 t0 = *(const float4*)(Arow);
            float4 t1 = *(const float4*)(Arow + 4);
            float4 t2 = *(const float4*)(Arow + 8);
            float4 t3 = *(const float4*)(Arow + 12);
            unsigned long long ap[8];
            ap[0] = ((unsigned long long*)&t0)[0]; ap[1] = ((unsigned long long*)&t0)[1];
            ap[2] = ((unsigned long long*)&t1)[0]; ap[3] = ((unsigned long long*)&t1)[1];
            ap[4] = ((unsigned long long*)&t2)[0]; ap[5] = ((unsigned long long*)&t2)[1];
            ap[6] = ((unsigned long long*)&t3)[0]; ap[7] = ((unsigned long long*)&t3)[1];
            float4 bv = *(const float4*)&Bb[kk * 128 + tx * 4];
            unsigned long long bb[4];
            bb[0] = bcast2(bv.x); bb[1] = bcast2(bv.y);
            bb[2] = bcast2(bv.z); bb[3] = bcast2(bv.w);
            #pragma unroll
            for (int p = 0; p < 8; p++) {
                fma2(acc2[p][0], ap[p], bb[0]);
                fma2(acc2[p][1], ap[p], bb[1]);
                fma2(acc2[p][2], ap[p], bb[2]);
                fma2(acc2[p][3], ap[p], bb[3]);
            }
        }
        buf ^= 1;
    }

    // epilogue: unpack pairs -> two float4 row stores per pair
    #pragma unroll
    for (int p = 0; p < 8; p++) {
        int m = m0 + ty * 16 + p * 2;
        float2 f0 = *(float2*)&acc2[p][0];
        float2 f1 = *(float2*)&acc2[p][1];
        float2 f2 = *(float2*)&acc2[p][2];
        float2 f3 = *(float2*)&acc2[p][3];
        float4 r0 = make_float4(f0.x, f1.x, f2.x, f3.x);   // row m
        float4 r1 = make_float4(f0.y, f1.y, f2.y, f3.y);   // row m+1
        *(float4*)&Cc[(size_t)m * L3 + n0 + tx * 4]       = r0;
        *(float4*)&Cc[(size_t)(m + 1) * L3 + n0 + tx * 4] = r1;
    }
}

// ---------------- 5a) x-pass: G[r][c] = A[c-1] + B[c] + C[c+1], 4 rows/block -
#define SRS 2312
__global__ void gpass1_kernel() {
    __shared__ __align__(16) float sR[6 * SRS];
    int r0 = blockIdx.x * 4, b = blockIdx.y;
    const float* Pb = g_P + (size_t)b * L3 * L3;
    float* Gb = g_G + (size_t)b * L3 * L3;
    int tid = threadIdx.x;

    #pragma unroll
    for (int i = 0; i < 6; i++) {
        int rr = min(max(r0 - 1 + i, 0), L3 - 1);   // clamped rows never used
        const float4* src = (const float4*)(Pb + (size_t)rr * L3);
        float4* dst = (float4*)&sR[i * SRS + 4];
        for (int g = tid; g < 576; g += 256) dst[g] = src[g];
    }
    __syncthreads();

    #pragma unroll
    for (int j = 0; j < 4; j++) {
        int r = r0 + j;
        int xq = r % H3;
        const float* Aj = &sR[j * SRS + 4];
        const float* Bj = &sR[(j + 1) * SRS + 4];
        const float* Cj = &sR[(j + 2) * SRS + 4];
        float* gr = Gb + (size_t)r * L3;
        bool hasA = (xq != 0), hasC = (xq != H3 - 1);

        if (hasA && hasC) {
            for (int g = tid; g < 576; g += 256) {
                int c = g * 4;
                int m = (g % 12) * 4;
                float4 bv = *(const float4*)&Bj[c];
                float a0 = (m != 0) ? Aj[c - 1] : 0.f;
                float c3 = (m != 44) ? Cj[c + 4] : 0.f;
                float4 o;
                o.x = a0        + bv.x + Cj[c + 1];
                o.y = Aj[c]     + bv.y + Cj[c + 2];
                o.z = Aj[c + 1] + bv.z + Cj[c + 3];
                o.w = Aj[c + 2] + bv.w + c3;
                *(float4*)&gr[c] = o;
            }
        } else if (!hasA) {
            for (int g = tid; g < 576; g += 256) {
                int c = g * 4;
                int m = (g % 12) * 4;
                float4 bv = *(const float4*)&Bj[c];
                float c3 = (m != 44) ? Cj[c + 4] : 0.f;
                float4 o;
                o.x = bv.x + Cj[c + 1];
                o.y = bv.y + Cj[c + 2];
                o.z = bv.z + Cj[c + 3];
                o.w = bv.w + c3;
                *(float4*)&gr[c] = o;
            }
        } else {
            for (int g = tid; g < 576; g += 256) {
                int c = g * 4;
                int m = (g % 12) * 4;
                float4 bv = *(const float4*)&Bj[c];
                float a0 = (m != 0) ? Aj[c - 1] : 0.f;
                float4 o;
                o.x = a0        + bv.x;
                o.y = Aj[c]     + bv.y;
                o.z = Aj[c + 1] + bv.z;
                o.w = Aj[c + 2] + bv.w;
                *(float4*)&gr[c] = o;
            }
        }
    }
    pdl_launch_dependents();
}

// ---------------- 5b) y-pass + max/argmax (hoisted-load 3 passes) ------------
__global__ void maxarg_kernel(float* __restrict__ outS) {
    int b = blockIdx.y, lq = blockIdx.x;
    int yq = lq / H3;
    const float4* Gb4 = (const float4*)(g_G + (size_t)b * L3 * L3);
    const float4* z4p = (const float4*)g_zero;

    const float4* rb[3];
    bool qv[3];
    #pragma unroll
    for (int t = 0; t < 3; t++) {
        int di = t - 1;
        qv[t] = ((unsigned)(yq + di) < H3);
        rb[t] = qv[t] ? (Gb4 + (size_t)(lq + 48 * di) * 576 + 12 * di) : z4p;
    }
    const float4* rnk4 = (const float4*)&g_nrm[1][b * L3];

    pdl_wait();     // g_G from gpass1 must be visible before loads

    const int tid = threadIdx.x;
    float best = -1e30f; int bi = 0;
    const float4 z4 = make_float4(0.f, 0.f, 0.f, 0.f);

    // ---- hoist ALL pass-1 + pass-2 loads before any compare (MLP ~10) ----
    const int giA = tid;            // pass 1: 0..255   (yk<=46 always; yk>=1 iff gi>=12)
    const int giB = tid + 256;      // pass 2: 256..511 (no yk masks needed)
    bool k0A = qv[0] && (giA >= 12);

    float4 a0 = k0A   ? rb[0][giA] : z4;
    float4 a1 = qv[1] ? rb[1][giA] : z4;
    float4 a2 = qv[2] ? rb[2][giA] : z4;
    float4 b0 = qv[0] ? rb[0][giB] : z4;
    float4 b1 = qv[1] ? rb[1][giB] : z4;
    float4 b2 = qv[2] ? rb[2][giB] : z4;
    float4 rkA = rnk4[giA];
    float4 rkB = rnk4[giB];

    // pass 1 compares
    {
        float s0 = (a0.x + a1.x + a2.x) * rkA.x;
        float s1 = (a0.y + a1.y + a2.y) * rkA.y;
        float s2 = (a0.z + a1.z + a2.z) * rkA.z;
        float s3 = (a0.w + a1.w + a2.w) * rkA.w;
        int lk = giA * 4;
        if (s0 > best) { best = s0; bi = lk; }
        if (s1 > best) { best = s1; bi = lk + 1; }
        if (s2 > best) { best = s2; bi = lk + 2; }
        if (s3 > best) { best = s3; bi = lk + 3; }
    }
    // pass 2 compares
    {
        float s0 = (b0.x + b1.x + b2.x) * rkB.x;
        float s1 = (b0.y + b1.y + b2.y) * rkB.y;
        float s2 = (b0.z + b1.z + b2.z) * rkB.z;
        float s3 = (b0.w + b1.w + b2.w) * rkB.w;
        int lk = giB * 4;
        if (s0 > best) { best = s0; bi = lk; }
        if (s1 > best) { best = s1; bi = lk + 1; }
        if (s2 > best) { best = s2; bi = lk + 2; }
        if (s3 > best) { best = s3; bi = lk + 3; }
    }
    // pass 3: gi = tid+512 (512..575), only tid<64. yk>=1 always; yk<=46 iff gi<564.
    if (tid < 64) {
        int gi = tid + 512;
        bool k2 = qv[2] && (gi < 564);
        float4 v0 = qv[0] ? rb[0][gi] : z4;
        float4 v1 = qv[1] ? rb[1][gi] : z4;
        float4 v2 = k2    ? rb[2][gi] : z4;
        float4 rk = rnk4[gi];
        float s0 = (v0.x + v1.x + v2.x) * rk.x;
        float s1 = (v0.y + v1.y + v2.y) * rk.y;
        float s2 = (v0.z + v1.z + v2.z) * rk.z;
        float s3 = (v0.w + v1.w + v2.w) * rk.w;
        int lk = gi * 4;
        if (s0 > best) { best = s0; bi = lk; }
        if (s1 > best) { best = s1; bi = lk + 1; }
        if (s2 > best) { best = s2; bi = lk + 2; }
        if (s3 > best) { best = s3; bi = lk + 3; }
    }

    __shared__ float sv[256];
    __shared__ int   si[256];
    sv[tid] = best; si[tid] = bi;
    __syncthreads();
    for (int st = 128; st > 0; st >>= 1) {
        if (tid < st) {
            float o = sv[tid + st]; int oi = si[tid + st];
            if (o > sv[tid] || (o == sv[tid] && oi < si[tid])) {
                sv[tid] = o; si[tid] = oi;
            }
        }
        __syncthreads();
    }
    if (tid == 0) {
        g_idx[b * L3 + lq] = si[0];
        outS[b * L3 + lq]  = sv[0] / g_nrm[0][b * L3 + lq];
    }
    pdl_launch_dependents();
}

// ---------------- 6) merged gather + fold-normalize (all 3 levels) -----------
__global__ void __launch_bounds__(256) transfer_kernel(float* __restrict__ outT3,
                                                       float* __restrict__ outT2,
                                                       float* __restrict__ outT1) {
    __shared__ __align__(16) float acc[3456];    // xpc*(C+8) <= 3456 floats
    __shared__ __align__(16) int4 ent[3][14];    // {dxs, base4, ok, pad}
    __shared__ float sinv[12];
    int j = blockIdx.x;
    int tid = threadIdx.x;

    // segment decode
    const float* clT; float* out; int C, W, ls, xpc, b, y, zc;
    int seg;
    if (j < XB3) {
        seg = 0;
        clT = g_cl3T; out = outT3; C = C3; W = H3; ls = 0; xpc = 12;
        y = j % H3; b = (j / H3) & 3; zc = j / (H3 * 4);
    } else if (j < XB3 + XB2) {
        seg = 1;
        int q = j - XB3;
        clT = g_cl2T; out = outT2; C = C2; W = H2; ls = 1; xpc = 24;
        y = q % H2; b = (q / H2) & 3; zc = q / (H2 * 4);
    } else {
        seg = 2;
        int q = j - XB3 - XB2;
        clT = g_cl1T; out = outT1; C = C1; W = H1; ls = 2; xpc = 48;
        y = q % H1; b = (q / H1) & 3; zc = q / (H1 * 4);
    }
    int xlo = zc * xpc;
    int cpg  = C >> 2;
    int cg   = tid & (cpg - 1);
    int xsub = tid / cpg;
    int ppp  = 256 / cpg;
    int astr = C + 8;

    int tyq  = y >> ls;
    int txq0 = xlo >> ls;
    const int* idxb = g_idx + b * L3;

    pdl_wait();     // g_idx from maxarg must be visible

    if (tid < 42) {
        int a = tid / 14, xi = tid % 14;
        int xq = txq0 - 1 + xi;
        int yq = tyq - 1 + a;
        int dxs = 0, base4 = 0, ok = 0;
        if ((unsigned)xq < H3 && (unsigned)yq < H3) {
            int idx = idxb[yq * H3 + xq];
            int yk = idx / H3, xk = idx % H3;
            int ys = y + ((yk - yq) << ls);
            if ((unsigned)ys < (unsigned)W) {
                ok = 1;
                base4 = ys * W * (C >> 2);
            }
            dxs = (xk - xq) << ls;
        }
        ent[a][xi] = make_int4(dxs, base4, ok, 0);
    }
    if (tid < 12) {
        int txq = txq0 + tid;
        int nvx = 1 + (txq > 0) + (txq < H3 - 1);
        int nvy = 1 + (tyq > 0) + (tyq < H3 - 1);
        sinv[tid] = 1.0f / (float)(nvx * nvy);
    }
    __syncthreads();

    const float4* f4b = (const float4*)(clT + (size_t)b * W * W * C);

    for (int xo = 0; xo < xpc; xo += ppp) {
        int x = xlo + xo + xsub;
        int xib = (x >> ls) - txq0;
        float4 sum = make_float4(0.f, 0.f, 0.f, 0.f);
        #pragma unroll
        for (int a = 0; a < 3; a++) {
            #pragma unroll
            for (int dx = 0; dx < 3; dx++) {
                int4 e = ent[a][xib + dx];
                int xs = x + e.x;
                if (e.z && (unsigned)xs < (unsigned)W) {
                    float4 v = f4b[e.y + xs * cpg + cg];
                    sum.x += v.x; sum.y += v.y; sum.z += v.z; sum.w += v.w;
                }
            }
        }
        float ic = sinv[xib];
        *(float4*)&acc[(xo + xsub) * astr + cg * 4] =
            make_float4(sum.x * ic, sum.y * ic, sum.z * ic, sum.w * ic);
    }
    __syncthreads();

    // writeout with compile-time xpc per segment (div -> mul/shift)
    size_t ob = (size_t)b * C * W * W + (size_t)y * W + xlo;
    #define WRITEOUT(XPC_) do {                                            \
        for (int i = tid; i < C * (XPC_); i += 256) {                      \
            int c = i / (XPC_), x = i % (XPC_);                            \
            out[ob + (size_t)c * W * W + x] = acc[x * astr + c];           \
        }                                                                  \
    } while (0)
    if (seg == 0)      WRITEOUT(12);
    else if (seg == 1) WRITEOUT(24);
    else               WRITEOUT(48);
    #undef WRITEOUT
}

// ---------------- launch ------------------------------------------------------
static cudaError_t launch_pdl(void* func, dim3 grid, dim3 block, void** args,
                              size_t smem) {
    cudaLaunchConfig_t cfg = {};
    cfg.gridDim = grid;
    cfg.blockDim = block;
    cfg.dynamicSmemBytes = smem;
    cfg.stream = 0;
    cudaLaunchAttribute at;
    at.id = cudaLaunchAttributeProgrammaticStreamSerialization;
    at.val.programmaticStreamSerializationAllowed = 1;
    cfg.attrs = &at;
    cfg.numAttrs = 1;
    return cudaLaunchKernelExC(&cfg, func, args);
}

extern "C" void kernel_launch(void* const* d_in, const int* in_sizes, int n_in,
                              void* d_out, int out_size) {
    const float* img = (const float*)d_in[0];   // dh_img_lv3 [4,256,48,48]
    const float* ref = (const float*)d_in[1];   // dh_ref_lv3 [4,256,48,48]
    const float* cl1 = (const float*)d_in[2];   // cl_ref_lv1 [4,64,192,192]
    const float* cl2 = (const float*)d_in[3];   // cl_ref_lv2 [4,128,96,96]
    const float* cl3 = (const float*)d_in[4];   // cl_ref_lv3 [4,256,48,48]

    float* outS  = (float*)d_out;               // [4,1,48,48]
    float* outT3 = outS  + BB * L3;             // [4,256,48,48]
    float* outT2 = outT3 + (size_t)BB * C3 * L3;    // [4,128,96,96]
    float* outT1 = outT2 + (size_t)BB * C2 * L2n;   // [4,64,192,192]

    cudaFuncSetAttribute(gemm_kernel,
                         cudaFuncAttributeMaxDynamicSharedMemorySize, GEMM_SMEM);

    // 0: side work FIRST (normal launch); signals dependents at start
    side_kernel<<<NSIDE, 256>>>(img, ref, cl1, cl2, cl3);

    // 1: GEMM as PSS dependent — back-fills SMs as side blocks drain
    {
        void* args[] = { (void*)&img, (void*)&ref };
        if (launch_pdl((void*)gemm_kernel, dim3(L3 / 128, L3 / 128, BB),
                       dim3(256), args, GEMM_SMEM) != cudaSuccess) {
            gemm_kernel<<<dim3(L3 / 128, L3 / 128, BB), 256, GEMM_SMEM>>>(img, ref);
        }
    }

    // 2: x-pass (NORMAL launch: hard barrier on side + gemm)
    gpass1_kernel<<<dim3(L3 / 4, BB), 256>>>();

    // 3: y-pass + argmax (PSS after gpass1; pdl_wait before g_G reads)
    {
        void* args[] = { (void*)&outS };
        if (launch_pdl((void*)maxarg_kernel, dim3(L3, BB), dim3(256), args, 0)
            != cudaSuccess) {
            maxarg_kernel<<<dim3(L3, BB), 256>>>(outS);
        }
    }

    // 4: all three transfers in one launch (PSS after maxarg; pdl_wait before g_idx)
    {
        void* args[] = { (void*)&outT3, (void*)&outT2, (void*)&outT1 };
        if (launch_pdl((void*)transfer_kernel, dim3(NXFER), dim3(256), args, 0)
            != cudaSuccess) {
            transfer_kernel<<<NXFER, 256>>>(outT3, outT2, outT1);
        }
    }
}